// round 3
// baseline (speedup 1.0000x reference)
#include <cuda_runtime.h>
#include <math.h>

#define BB   4
#define SS   2048
#define DD   1024
#define HH   16
#define DHH  64
#define MTOT (BB*SS)

// Scratch (allocation-free rule: __device__ globals)
__device__ float g_q [MTOT*DD];
__device__ float g_k [MTOT*DD];
__device__ float g_v [MTOT*DD];
__device__ float g_ho[MTOT*DD];

// ---------------------------------------------------------------------------
// NT GEMM: C[m,n] = sum_k A[m,k] * W[n,k], M=8192, N=K=1024.
// 64x64 block tile, BK=16, 256 threads, 4x4 micro-tile.
// Smem stored transposed [k][m] with stride 68 (16B-aligned rows -> LDS128).
// applyRope: fuse RoPE epilogue (pos = row % S, d = col % 64).
// ---------------------------------------------------------------------------
__global__ __launch_bounds__(256) void gemm_nt_kernel(
    const float* __restrict__ A, const float* __restrict__ W,
    float* __restrict__ C, int applyRope)
{
    __shared__ __align__(16) float As[16][68];
    __shared__ __align__(16) float Ws[16][68];

    const int bm  = blockIdx.y * 64;
    const int bn  = blockIdx.x * 64;
    const int tid = threadIdx.x;
    const int tx  = tid & 15;
    const int ty  = tid >> 4;
    const int lr  = tid >> 2;          // 0..63
    const int lc  = (tid & 3) << 2;    // 0,4,8,12

    const float* Ap = A + (size_t)(bm + lr) * DD + lc;
    const float* Wp = W + (size_t)(bn + lr) * DD + lc;

    float acc[4][4];
    #pragma unroll
    for (int i = 0; i < 4; i++)
        #pragma unroll
        for (int j = 0; j < 4; j++) acc[i][j] = 0.f;

    for (int k0 = 0; k0 < DD; k0 += 16) {
        float4 av = *(const float4*)(Ap + k0);
        float4 wv = *(const float4*)(Wp + k0);
        As[lc+0][lr] = av.x; As[lc+1][lr] = av.y;
        As[lc+2][lr] = av.z; As[lc+3][lr] = av.w;
        Ws[lc+0][lr] = wv.x; Ws[lc+1][lr] = wv.y;
        Ws[lc+2][lr] = wv.z; Ws[lc+3][lr] = wv.w;
        __syncthreads();

        #pragma unroll
        for (int kk = 0; kk < 16; kk++) {
            float4 a4 = *(const float4*)&As[kk][ty << 2];
            float4 b4 = *(const float4*)&Ws[kk][tx << 2];
            float ar[4] = {a4.x, a4.y, a4.z, a4.w};
            float br[4] = {b4.x, b4.y, b4.z, b4.w};
            #pragma unroll
            for (int i = 0; i < 4; i++)
                #pragma unroll
                for (int j = 0; j < 4; j++)
                    acc[i][j] = fmaf(ar[i], br[j], acc[i][j]);
        }
        __syncthreads();
    }

    if (applyRope) {
        #pragma unroll
        for (int i = 0; i < 4; i++) {
            int   row = bm + (ty << 2) + i;
            float pos = (float)(row & (SS - 1));
            #pragma unroll
            for (int jp = 0; jp < 4; jp += 2) {
                int   d    = (bn + (tx << 2) + jp) & (DHH - 1);
                float freq = powf(10000.0f, -(float)d * (1.0f / 64.0f));
                float sn, cs;
                sincosf(pos * freq, &sn, &cs);
                float e = acc[i][jp], o = acc[i][jp + 1];
                acc[i][jp]     = e * cs - o * sn;
                acc[i][jp + 1] = e * sn + o * cs;
            }
        }
    }

    #pragma unroll
    for (int i = 0; i < 4; i++) {
        float4 r;
        r.x = acc[i][0]; r.y = acc[i][1]; r.z = acc[i][2]; r.w = acc[i][3];
        *(float4*)(C + (size_t)(bm + (ty << 2) + i) * DD + bn + (tx << 2)) = r;
    }
}

// ---------------------------------------------------------------------------
// Causal flash attention, fp32 SIMT.
// Grid: (S/64, B*H). Block: 256 threads. 64 query rows per block.
// Smem: Qs [d][r] stride 68 (transposed), KVs (K transposed / V natural,
// stride 68), Ps [r][c] stride 65. Online softmax in registers.
// ---------------------------------------------------------------------------
#define QST 68
#define PST 65

__global__ __launch_bounds__(256) void attn_kernel(
    const float* __restrict__ Q, const float* __restrict__ K,
    const float* __restrict__ V, float* __restrict__ O)
{
    extern __shared__ __align__(16) float sm[];
    float* Qs  = sm;                  // 64*68
    float* KVs = sm + 64 * QST;       // 64*68
    float* Ps  = sm + 2 * 64 * QST;   // 64*65

    const int qb  = blockIdx.x;
    const int b   = blockIdx.y >> 4;
    const int h   = blockIdx.y & 15;
    const int tid = threadIdx.x;
    const int tx  = tid & 15;
    const int ty  = tid >> 4;
    const size_t base = ((size_t)b * SS) * DD + h * DHH;

    // Load Q tile transposed, pre-scaled by 1/sqrt(DH)
    for (int t = tid; t < 1024; t += 256) {
        int r = t >> 4, d4 = (t & 15) << 2;
        float4 qv = *(const float4*)(Q + base + (size_t)(qb * 64 + r) * DD + d4);
        Qs[(d4 + 0) * QST + r] = qv.x * 0.125f;
        Qs[(d4 + 1) * QST + r] = qv.y * 0.125f;
        Qs[(d4 + 2) * QST + r] = qv.z * 0.125f;
        Qs[(d4 + 3) * QST + r] = qv.w * 0.125f;
    }

    float m_i[4], l_i[4], o_acc[4][4];
    #pragma unroll
    for (int i = 0; i < 4; i++) {
        m_i[i] = -1e30f; l_i[i] = 0.f;
        #pragma unroll
        for (int j = 0; j < 4; j++) o_acc[i][j] = 0.f;
    }

    for (int kb = 0; kb <= qb; kb++) {
        __syncthreads();  // prior P/V reads done (and Q load on first iter)

        // K tile, transposed
        for (int t = tid; t < 1024; t += 256) {
            int c = t >> 4, d4 = (t & 15) << 2;
            float4 kv = *(const float4*)(K + base + (size_t)(kb * 64 + c) * DD + d4);
            KVs[(d4 + 0) * QST + c] = kv.x;
            KVs[(d4 + 1) * QST + c] = kv.y;
            KVs[(d4 + 2) * QST + c] = kv.z;
            KVs[(d4 + 3) * QST + c] = kv.w;
        }
        __syncthreads();

        // Scores S = (Q*scale) K^T, 4x4 per thread
        float s[4][4];
        #pragma unroll
        for (int i = 0; i < 4; i++)
            #pragma unroll
            for (int j = 0; j < 4; j++) s[i][j] = 0.f;

        #pragma unroll 8
        for (int d = 0; d < 64; d++) {
            float4 a4 = *(const float4*)&Qs [d * QST + (ty << 2)];
            float4 b4 = *(const float4*)&KVs[d * QST + (tx << 2)];
            float ar[4] = {a4.x, a4.y, a4.z, a4.w};
            float br[4] = {b4.x, b4.y, b4.z, b4.w};
            #pragma unroll
            for (int i = 0; i < 4; i++)
                #pragma unroll
                for (int j = 0; j < 4; j++)
                    s[i][j] = fmaf(ar[i], br[j], s[i][j]);
        }

        if (kb == qb) {  // diagonal block: mask key > query
            #pragma unroll
            for (int i = 0; i < 4; i++)
                #pragma unroll
                for (int j = 0; j < 4; j++)
                    if ((tx << 2) + j > (ty << 2) + i) s[i][j] = -1e30f;
        }

        // Online softmax update (row groups = 16 consecutive lanes)
        #pragma unroll
        for (int i = 0; i < 4; i++) {
            float mx = fmaxf(fmaxf(s[i][0], s[i][1]), fmaxf(s[i][2], s[i][3]));
            #pragma unroll
            for (int off = 1; off < 16; off <<= 1)
                mx = fmaxf(mx, __shfl_xor_sync(0xffffffffu, mx, off));
            float mnew = fmaxf(m_i[i], mx);
            float corr = __expf(m_i[i] - mnew);
            float rs = 0.f;
            #pragma unroll
            for (int j = 0; j < 4; j++) {
                s[i][j] = __expf(s[i][j] - mnew);
                rs += s[i][j];
            }
            #pragma unroll
            for (int off = 1; off < 16; off <<= 1)
                rs += __shfl_xor_sync(0xffffffffu, rs, off);
            l_i[i] = l_i[i] * corr + rs;
            m_i[i] = mnew;
            #pragma unroll
            for (int j = 0; j < 4; j++) o_acc[i][j] *= corr;
        }
        __syncthreads();  // done reading KVs as K

        // Write P; load V tile (natural layout) into the same buffer
        #pragma unroll
        for (int i = 0; i < 4; i++)
            #pragma unroll
            for (int j = 0; j < 4; j++)
                Ps[((ty << 2) + i) * PST + (tx << 2) + j] = s[i][j];

        for (int t = tid; t < 1024; t += 256) {
            int r = t >> 4, d4 = (t & 15) << 2;
            float4 vv = *(const float4*)(V + base + (size_t)(kb * 64 + r) * DD + d4);
            *(float4*)&KVs[r * QST + d4] = vv;
        }
        __syncthreads();

        // O += P @ V
        #pragma unroll 4
        for (int jk = 0; jk < 64; jk++) {
            float a0 = Ps[((ty << 2) + 0) * PST + jk];
            float a1 = Ps[((ty << 2) + 1) * PST + jk];
            float a2 = Ps[((ty << 2) + 2) * PST + jk];
            float a3 = Ps[((ty << 2) + 3) * PST + jk];
            float4 b4 = *(const float4*)&KVs[jk * QST + (tx << 2)];
            float br[4] = {b4.x, b4.y, b4.z, b4.w};
            float ar[4] = {a0, a1, a2, a3};
            #pragma unroll
            for (int i = 0; i < 4; i++)
                #pragma unroll
                for (int j = 0; j < 4; j++)
                    o_acc[i][j] = fmaf(ar[i], br[j], o_acc[i][j]);
        }
    }

    #pragma unroll
    for (int i = 0; i < 4; i++) {
        float inv = 1.0f / l_i[i];
        float4 r;
        r.x = o_acc[i][0] * inv; r.y = o_acc[i][1] * inv;
        r.z = o_acc[i][2] * inv; r.w = o_acc[i][3] * inv;
        *(float4*)(O + base + (size_t)(qb * 64 + (ty << 2) + i) * DD + (tx << 2)) = r;
    }
}

// ---------------------------------------------------------------------------
extern "C" void kernel_launch(void* const* d_in, const int* in_sizes, int n_in,
                              void* d_out, int out_size)
{
    const float* x  = (const float*)d_in[0];
    const float* Wq = (const float*)d_in[1];
    const float* Wk = (const float*)d_in[2];
    const float* Wv = (const float*)d_in[3];
    const float* Wo = (const float*)d_in[4];
    float* out = (float*)d_out;

    float *q, *k, *v, *ho;
    cudaGetSymbolAddress((void**)&q,  g_q);
    cudaGetSymbolAddress((void**)&k,  g_k);
    cudaGetSymbolAddress((void**)&v,  g_v);
    cudaGetSymbolAddress((void**)&ho, g_ho);

    dim3 gg(DD / 64, MTOT / 64);  // (16, 128)
    gemm_nt_kernel<<<gg, 256>>>(x, Wq, q, 1);
    gemm_nt_kernel<<<gg, 256>>>(x, Wk, k, 1);
    gemm_nt_kernel<<<gg, 256>>>(x, Wv, v, 0);

    size_t smem = (size_t)(2 * 64 * QST + 64 * PST) * sizeof(float);  // 51456 B
    cudaFuncSetAttribute(attn_kernel,
                         cudaFuncAttributeMaxDynamicSharedMemorySize, (int)smem);
    attn_kernel<<<dim3(SS / 64, BB * HH), 256, smem>>>(q, k, v, ho);

    gemm_nt_kernel<<<gg, 256>>>(ho, Wo, out, 0);
}

// round 8
// speedup vs baseline: 1.6899x; 1.6899x over previous
#include <cuda_runtime.h>
#include <math.h>
#include <stdint.h>

#define BB   4
#define SS   2048
#define DD   1024
#define HH   16
#define DHH  64
#define MTOT (BB*SS)

// Scratch (allocation-free rule: __device__ globals)
__device__ float g_q [MTOT*DD];
__device__ float g_k [MTOT*DD];
__device__ float g_v [MTOT*DD];
__device__ float g_ho[MTOT*DD];

// ---------------------------------------------------------------------------
// tf32 helpers
// ---------------------------------------------------------------------------
__device__ __forceinline__ uint32_t f2tf(float x) {
    uint32_t u;
    asm("cvt.rna.tf32.f32 %0, %1;" : "=r"(u) : "f"(x));
    return u;
}

__device__ __forceinline__ void mma_tf32(float* c, const uint32_t* a, const uint32_t* b) {
    asm volatile(
        "mma.sync.aligned.m16n8k8.row.col.f32.tf32.tf32.f32 "
        "{%0,%1,%2,%3}, {%4,%5,%6,%7}, {%8,%9}, {%0,%1,%2,%3};"
        : "+f"(c[0]), "+f"(c[1]), "+f"(c[2]), "+f"(c[3])
        : "r"(a[0]), "r"(a[1]), "r"(a[2]), "r"(a[3]),
          "r"(b[0]), "r"(b[1]));
}

// ---------------------------------------------------------------------------
// NT GEMM via tf32 tensor cores: C[m,n] = sum_k A[m,k] * W[n,k]
// M=8192, N=K=1024. Block 128x128x32, 256 threads (8 warps, 2m x 4n),
// warp tile 64x32 = 4x4 mma tiles of m16n8k8.
// Smem XOR swizzle: element (row, k) stored at col k ^ (4*(row&7)).
//   -> STS128 writer conflict-free, LDS32 fragment reads conflict-free.
// Register prefetch overlaps LDG of next K-tile with MMA of current one.
// applyRope: RoPE fused in epilogue (C frag cols are (even,odd) pairs).
// ---------------------------------------------------------------------------
__global__ __launch_bounds__(256, 1) void gemm_tc(
    const float* __restrict__ A, const float* __restrict__ W,
    float* __restrict__ C, int applyRope)
{
    __shared__ __align__(16) uint32_t As[128 * 32];
    __shared__ __align__(16) uint32_t Bs[128 * 32];

    const int tid  = threadIdx.x;
    const int bm   = blockIdx.y * 128;
    const int bn   = blockIdx.x * 128;
    const int wid  = tid >> 5;
    const int lane = tid & 31;
    const int wm   = wid >> 2;      // 0..1
    const int wn   = wid & 3;       // 0..3
    const int li   = lane >> 2;     // 0..7
    const int lc   = lane & 3;      // 0..3

    // writer assignment: thread covers rows r0+32*it (it=0..3), float4 col q
    const int r0 = tid >> 3;        // 0..31
    const int q  = tid & 7;         // 0..7
    const int xq = q ^ (r0 & 7);    // swizzled float4 column

    const float4* Ag = (const float4*)(A + (size_t)(bm + r0) * DD) + q;
    const float4* Bg = (const float4*)(W + (size_t)(bn + r0) * DD) + q;

    uint4* As4 = (uint4*)As;
    uint4* Bs4 = (uint4*)Bs;

    float acc[4][4][4];
    #pragma unroll
    for (int mt = 0; mt < 4; mt++)
        #pragma unroll
        for (int nt = 0; nt < 4; nt++)
            #pragma unroll
            for (int r = 0; r < 4; r++) acc[mt][nt][r] = 0.f;

    // prefetch K-tile 0
    float4 pa[4], pb[4];
    #pragma unroll
    for (int it = 0; it < 4; it++) {
        pa[it] = Ag[(size_t)8192 * it];   // +32 rows = 32*256 float4
        pb[it] = Bg[(size_t)8192 * it];
    }

    for (int kt0 = 0; kt0 < 32; kt0++) {
        // stage registers -> smem (cvt to tf32)
        #pragma unroll
        for (int it = 0; it < 4; it++) {
            uint4 ua, ub;
            ua.x = f2tf(pa[it].x); ua.y = f2tf(pa[it].y);
            ua.z = f2tf(pa[it].z); ua.w = f2tf(pa[it].w);
            ub.x = f2tf(pb[it].x); ub.y = f2tf(pb[it].y);
            ub.z = f2tf(pb[it].z); ub.w = f2tf(pb[it].w);
            As4[(r0 + 32 * it) * 8 + xq] = ua;
            Bs4[(r0 + 32 * it) * 8 + xq] = ub;
        }
        __syncthreads();

        // prefetch next K-tile while computing this one
        if (kt0 < 31) {
            #pragma unroll
            for (int it = 0; it < 4; it++) {
                pa[it] = Ag[(size_t)(kt0 + 1) * 8 + (size_t)8192 * it];
                pb[it] = Bg[(size_t)(kt0 + 1) * 8 + (size_t)8192 * it];
            }
        }

        // 4 k8 steps
        #pragma unroll
        for (int kt = 0; kt < 4; kt++) {
            const int ka = (kt * 8 + lc)     ^ (li * 4);
            const int kb = (kt * 8 + lc + 4) ^ (li * 4);

            uint32_t af[4][4];
            #pragma unroll
            for (int mt = 0; mt < 4; mt++) {
                int row = wm * 64 + mt * 16 + li;
                af[mt][0] = As[row * 32 + ka];
                af[mt][1] = As[(row + 8) * 32 + ka];
                af[mt][2] = As[row * 32 + kb];
                af[mt][3] = As[(row + 8) * 32 + kb];
            }
            uint32_t bf[4][2];
            #pragma unroll
            for (int nt = 0; nt < 4; nt++) {
                int n = wn * 32 + nt * 8 + li;
                bf[nt][0] = Bs[n * 32 + ka];
                bf[nt][1] = Bs[n * 32 + kb];
            }
            #pragma unroll
            for (int mt = 0; mt < 4; mt++)
                #pragma unroll
                for (int nt = 0; nt < 4; nt++)
                    mma_tf32(acc[mt][nt], af[mt], bf[nt]);
        }
        __syncthreads();
    }

    // epilogue (+ fused RoPE on (even,odd) column pairs)
    #pragma unroll
    for (int mt = 0; mt < 4; mt++) {
        int rg = bm + wm * 64 + mt * 16 + li;
        #pragma unroll
        for (int nt = 0; nt < 4; nt++) {
            int cp = bn + wn * 32 + nt * 8 + lc * 2;   // even column
            float c0 = acc[mt][nt][0], c1 = acc[mt][nt][1];
            float c2 = acc[mt][nt][2], c3 = acc[mt][nt][3];
            if (applyRope) {
                int   d    = cp & (DHH - 1);
                float freq = powf(10000.0f, -(float)d * (1.0f / 64.0f));
                float s0, co0, s1, co1;
                sincosf((float)(rg & (SS - 1)) * freq, &s0, &co0);
                sincosf((float)((rg + 8) & (SS - 1)) * freq, &s1, &co1);
                float t;
                t  = c0 * co0 - c1 * s0;  c1 = c0 * s0 + c1 * co0;  c0 = t;
                t  = c2 * co1 - c3 * s1;  c3 = c2 * s1 + c3 * co1;  c2 = t;
            }
            *(float2*)(C + (size_t)rg * DD + cp)       = make_float2(c0, c1);
            *(float2*)(C + (size_t)(rg + 8) * DD + cp) = make_float2(c2, c3);
        }
    }
}

// ---------------------------------------------------------------------------
// Causal flash attention, fp32 SIMT (unchanged, known-correct from R3 bench).
// ---------------------------------------------------------------------------
#define QST 68
#define PST 65

__global__ __launch_bounds__(256) void attn_kernel(
    const float* __restrict__ Q, const float* __restrict__ K,
    const float* __restrict__ V, float* __restrict__ O)
{
    extern __shared__ __align__(16) float sm[];
    float* Qs  = sm;                  // 64*68
    float* KVs = sm + 64 * QST;       // 64*68
    float* Ps  = sm + 2 * 64 * QST;   // 64*65

    const int qb  = blockIdx.x;
    const int b   = blockIdx.y >> 4;
    const int h   = blockIdx.y & 15;
    const int tid = threadIdx.x;
    const int tx  = tid & 15;
    const int ty  = tid >> 4;
    const size_t base = ((size_t)b * SS) * DD + h * DHH;

    for (int t = tid; t < 1024; t += 256) {
        int r = t >> 4, d4 = (t & 15) << 2;
        float4 qv = *(const float4*)(Q + base + (size_t)(qb * 64 + r) * DD + d4);
        Qs[(d4 + 0) * QST + r] = qv.x * 0.125f;
        Qs[(d4 + 1) * QST + r] = qv.y * 0.125f;
        Qs[(d4 + 2) * QST + r] = qv.z * 0.125f;
        Qs[(d4 + 3) * QST + r] = qv.w * 0.125f;
    }

    float m_i[4], l_i[4], o_acc[4][4];
    #pragma unroll
    for (int i = 0; i < 4; i++) {
        m_i[i] = -1e30f; l_i[i] = 0.f;
        #pragma unroll
        for (int j = 0; j < 4; j++) o_acc[i][j] = 0.f;
    }

    for (int kb = 0; kb <= qb; kb++) {
        __syncthreads();

        for (int t = tid; t < 1024; t += 256) {
            int c = t >> 4, d4 = (t & 15) << 2;
            float4 kv = *(const float4*)(K + base + (size_t)(kb * 64 + c) * DD + d4);
            KVs[(d4 + 0) * QST + c] = kv.x;
            KVs[(d4 + 1) * QST + c] = kv.y;
            KVs[(d4 + 2) * QST + c] = kv.z;
            KVs[(d4 + 3) * QST + c] = kv.w;
        }
        __syncthreads();

        float s[4][4];
        #pragma unroll
        for (int i = 0; i < 4; i++)
            #pragma unroll
            for (int j = 0; j < 4; j++) s[i][j] = 0.f;

        #pragma unroll 8
        for (int d = 0; d < 64; d++) {
            float4 a4 = *(const float4*)&Qs [d * QST + (ty << 2)];
            float4 b4 = *(const float4*)&KVs[d * QST + (tx << 2)];
            float ar[4] = {a4.x, a4.y, a4.z, a4.w};
            float br[4] = {b4.x, b4.y, b4.z, b4.w};
            #pragma unroll
            for (int i = 0; i < 4; i++)
                #pragma unroll
                for (int j = 0; j < 4; j++)
                    s[i][j] = fmaf(ar[i], br[j], s[i][j]);
        }

        if (kb == qb) {
            #pragma unroll
            for (int i = 0; i < 4; i++)
                #pragma unroll
                for (int j = 0; j < 4; j++)
                    if ((tx << 2) + j > (ty << 2) + i) s[i][j] = -1e30f;
        }

        #pragma unroll
        for (int i = 0; i < 4; i++) {
            float mx = fmaxf(fmaxf(s[i][0], s[i][1]), fmaxf(s[i][2], s[i][3]));
            #pragma unroll
            for (int off = 1; off < 16; off <<= 1)
                mx = fmaxf(mx, __shfl_xor_sync(0xffffffffu, mx, off));
            float mnew = fmaxf(m_i[i], mx);
            float corr = __expf(m_i[i] - mnew);
            float rs = 0.f;
            #pragma unroll
            for (int j = 0; j < 4; j++) {
                s[i][j] = __expf(s[i][j] - mnew);
                rs += s[i][j];
            }
            #pragma unroll
            for (int off = 1; off < 16; off <<= 1)
                rs += __shfl_xor_sync(0xffffffffu, rs, off);
            l_i[i] = l_i[i] * corr + rs;
            m_i[i] = mnew;
            #pragma unroll
            for (int j = 0; j < 4; j++) o_acc[i][j] *= corr;
        }
        __syncthreads();

        #pragma unroll
        for (int i = 0; i < 4; i++)
            #pragma unroll
            for (int j = 0; j < 4; j++)
                Ps[((ty << 2) + i) * PST + (tx << 2) + j] = s[i][j];

        for (int t = tid; t < 1024; t += 256) {
            int r = t >> 4, d4 = (t & 15) << 2;
            float4 vv = *(const float4*)(V + base + (size_t)(kb * 64 + r) * DD + d4);
            *(float4*)&KVs[r * QST + d4] = vv;
        }
        __syncthreads();

        #pragma unroll 4
        for (int jk = 0; jk < 64; jk++) {
            float a0 = Ps[((ty << 2) + 0) * PST + jk];
            float a1 = Ps[((ty << 2) + 1) * PST + jk];
            float a2 = Ps[((ty << 2) + 2) * PST + jk];
            float a3 = Ps[((ty << 2) + 3) * PST + jk];
            float4 b4 = *(const float4*)&KVs[jk * QST + (tx << 2)];
            float br[4] = {b4.x, b4.y, b4.z, b4.w};
            float ar[4] = {a0, a1, a2, a3};
            #pragma unroll
            for (int i = 0; i < 4; i++)
                #pragma unroll
                for (int j = 0; j < 4; j++)
                    o_acc[i][j] = fmaf(ar[i], br[j], o_acc[i][j]);
        }
    }

    #pragma unroll
    for (int i = 0; i < 4; i++) {
        float inv = 1.0f / l_i[i];
        float4 r;
        r.x = o_acc[i][0] * inv; r.y = o_acc[i][1] * inv;
        r.z = o_acc[i][2] * inv; r.w = o_acc[i][3] * inv;
        *(float4*)(O + base + (size_t)(qb * 64 + (ty << 2) + i) * DD + (tx << 2)) = r;
    }
}

// ---------------------------------------------------------------------------
extern "C" void kernel_launch(void* const* d_in, const int* in_sizes, int n_in,
                              void* d_out, int out_size)
{
    const float* x  = (const float*)d_in[0];
    const float* Wq = (const float*)d_in[1];
    const float* Wk = (const float*)d_in[2];
    const float* Wv = (const float*)d_in[3];
    const float* Wo = (const float*)d_in[4];
    float* out = (float*)d_out;

    float *q, *k, *v, *ho;
    cudaGetSymbolAddress((void**)&q,  g_q);
    cudaGetSymbolAddress((void**)&k,  g_k);
    cudaGetSymbolAddress((void**)&v,  g_v);
    cudaGetSymbolAddress((void**)&ho, g_ho);

    dim3 gg(DD / 128, MTOT / 128);  // (8, 64)
    gemm_tc<<<gg, 256>>>(x, Wq, q, 1);
    gemm_tc<<<gg, 256>>>(x, Wk, k, 1);
    gemm_tc<<<gg, 256>>>(x, Wv, v, 0);

    size_t smem = (size_t)(2 * 64 * QST + 64 * PST) * sizeof(float);  // 51456 B
    cudaFuncSetAttribute(attn_kernel,
                         cudaFuncAttributeMaxDynamicSharedMemorySize, (int)smem);
    attn_kernel<<<dim3(SS / 64, BB * HH), 256, smem>>>(q, k, v, ho);

    gemm_tc<<<gg, 256>>>(ho, Wo, out, 0);
}

// round 9
// speedup vs baseline: 3.2680x; 1.9338x over previous
#include <cuda_runtime.h>
#include <cuda_fp16.h>
#include <math.h>
#include <stdint.h>

#define BB   4
#define SS   2048
#define DD   1024
#define HH   16
#define DHH  64
#define MTOT (BB*SS)

// Scratch (allocation-free rule: __device__ globals)
__device__ float g_q [MTOT*DD];
__device__ float g_k [MTOT*DD];
__device__ float g_v [MTOT*DD];
__device__ float g_ho[MTOT*DD];

// ---------------------------------------------------------------------------
// mma helpers
// ---------------------------------------------------------------------------
__device__ __forceinline__ uint32_t f2tf(float x) {
    uint32_t u;
    asm("cvt.rna.tf32.f32 %0, %1;" : "=r"(u) : "f"(x));
    return u;
}

__device__ __forceinline__ void mma_tf32(float* c, const uint32_t* a, const uint32_t* b) {
    asm volatile(
        "mma.sync.aligned.m16n8k8.row.col.f32.tf32.tf32.f32 "
        "{%0,%1,%2,%3}, {%4,%5,%6,%7}, {%8,%9}, {%0,%1,%2,%3};"
        : "+f"(c[0]), "+f"(c[1]), "+f"(c[2]), "+f"(c[3])
        : "r"(a[0]), "r"(a[1]), "r"(a[2]), "r"(a[3]),
          "r"(b[0]), "r"(b[1]));
}

__device__ __forceinline__ void mma_f16(float* c, const uint32_t* a, const uint32_t* b) {
    asm volatile(
        "mma.sync.aligned.m16n8k16.row.col.f32.f16.f16.f32 "
        "{%0,%1,%2,%3}, {%4,%5,%6,%7}, {%8,%9}, {%0,%1,%2,%3};"
        : "+f"(c[0]), "+f"(c[1]), "+f"(c[2]), "+f"(c[3])
        : "r"(a[0]), "r"(a[1]), "r"(a[2]), "r"(a[3]),
          "r"(b[0]), "r"(b[1]));
}

__device__ __forceinline__ uint32_t packh2(float lo, float hi) {
    __half2 h = __floats2half2_rn(lo, hi);
    return *(uint32_t*)&h;
}

// ---------------------------------------------------------------------------
// NT GEMM via tf32 tensor cores (unchanged from R8 passing version).
// ---------------------------------------------------------------------------
__global__ __launch_bounds__(256, 1) void gemm_tc(
    const float* __restrict__ A, const float* __restrict__ W,
    float* __restrict__ C, int applyRope)
{
    __shared__ __align__(16) uint32_t As[128 * 32];
    __shared__ __align__(16) uint32_t Bs[128 * 32];

    const int tid  = threadIdx.x;
    const int bm   = blockIdx.y * 128;
    const int bn   = blockIdx.x * 128;
    const int wid  = tid >> 5;
    const int lane = tid & 31;
    const int wm   = wid >> 2;
    const int wn   = wid & 3;
    const int li   = lane >> 2;
    const int lc   = lane & 3;

    const int r0 = tid >> 3;
    const int q  = tid & 7;
    const int xq = q ^ (r0 & 7);

    const float4* Ag = (const float4*)(A + (size_t)(bm + r0) * DD) + q;
    const float4* Bg = (const float4*)(W + (size_t)(bn + r0) * DD) + q;

    uint4* As4 = (uint4*)As;
    uint4* Bs4 = (uint4*)Bs;

    float acc[4][4][4];
    #pragma unroll
    for (int mt = 0; mt < 4; mt++)
        #pragma unroll
        for (int nt = 0; nt < 4; nt++)
            #pragma unroll
            for (int r = 0; r < 4; r++) acc[mt][nt][r] = 0.f;

    float4 pa[4], pb[4];
    #pragma unroll
    for (int it = 0; it < 4; it++) {
        pa[it] = Ag[(size_t)8192 * it];
        pb[it] = Bg[(size_t)8192 * it];
    }

    for (int kt0 = 0; kt0 < 32; kt0++) {
        #pragma unroll
        for (int it = 0; it < 4; it++) {
            uint4 ua, ub;
            ua.x = f2tf(pa[it].x); ua.y = f2tf(pa[it].y);
            ua.z = f2tf(pa[it].z); ua.w = f2tf(pa[it].w);
            ub.x = f2tf(pb[it].x); ub.y = f2tf(pb[it].y);
            ub.z = f2tf(pb[it].z); ub.w = f2tf(pb[it].w);
            As4[(r0 + 32 * it) * 8 + xq] = ua;
            Bs4[(r0 + 32 * it) * 8 + xq] = ub;
        }
        __syncthreads();

        if (kt0 < 31) {
            #pragma unroll
            for (int it = 0; it < 4; it++) {
                pa[it] = Ag[(size_t)(kt0 + 1) * 8 + (size_t)8192 * it];
                pb[it] = Bg[(size_t)(kt0 + 1) * 8 + (size_t)8192 * it];
            }
        }

        #pragma unroll
        for (int kt = 0; kt < 4; kt++) {
            const int ka = (kt * 8 + lc)     ^ (li * 4);
            const int kb = (kt * 8 + lc + 4) ^ (li * 4);

            uint32_t af[4][4];
            #pragma unroll
            for (int mt = 0; mt < 4; mt++) {
                int row = wm * 64 + mt * 16 + li;
                af[mt][0] = As[row * 32 + ka];
                af[mt][1] = As[(row + 8) * 32 + ka];
                af[mt][2] = As[row * 32 + kb];
                af[mt][3] = As[(row + 8) * 32 + kb];
            }
            uint32_t bf[4][2];
            #pragma unroll
            for (int nt = 0; nt < 4; nt++) {
                int n = wn * 32 + nt * 8 + li;
                bf[nt][0] = Bs[n * 32 + ka];
                bf[nt][1] = Bs[n * 32 + kb];
            }
            #pragma unroll
            for (int mt = 0; mt < 4; mt++)
                #pragma unroll
                for (int nt = 0; nt < 4; nt++)
                    mma_tf32(acc[mt][nt], af[mt], bf[nt]);
        }
        __syncthreads();
    }

    #pragma unroll
    for (int mt = 0; mt < 4; mt++) {
        int rg = bm + wm * 64 + mt * 16 + li;
        #pragma unroll
        for (int nt = 0; nt < 4; nt++) {
            int cp = bn + wn * 32 + nt * 8 + lc * 2;
            float c0 = acc[mt][nt][0], c1 = acc[mt][nt][1];
            float c2 = acc[mt][nt][2], c3 = acc[mt][nt][3];
            if (applyRope) {
                int   d    = cp & (DHH - 1);
                float freq = powf(10000.0f, -(float)d * (1.0f / 64.0f));
                float s0, co0, s1, co1;
                sincosf((float)(rg & (SS - 1)) * freq, &s0, &co0);
                sincosf((float)((rg + 8) & (SS - 1)) * freq, &s1, &co1);
                float t;
                t  = c0 * co0 - c1 * s0;  c1 = c0 * s0 + c1 * co0;  c0 = t;
                t  = c2 * co1 - c3 * s1;  c3 = c2 * s1 + c3 * co1;  c2 = t;
            }
            *(float2*)(C + (size_t)rg * DD + cp)       = make_float2(c0, c1);
            *(float2*)(C + (size_t)(rg + 8) * DD + cp) = make_float2(c2, c3);
        }
    }
}

// ---------------------------------------------------------------------------
// Tensor-core causal flash attention.
// Grid (S/128, B*H), 256 threads = 8 warps, each warp owns 16 query rows.
// S = QK^T via tf32 m16n8k8 (Qs/Ks smem stride 68 -> conflict-free frags).
// P*V via fp16 m16n8k16: S C-frag layout == fp16 A-frag layout (no shuffles);
// V packed as half2 key-pairs Vp[kp][n], stride 72 -> conflict-free B-frags.
// Online softmax on C fragments (2 rows/thread, quad shfl reductions).
// ---------------------------------------------------------------------------
#define ATT_SMEM (128*68*4 + 64*68*4 + 32*72*4)   // 61440 B

__global__ __launch_bounds__(256, 1) void attn_tc(
    const float* __restrict__ Q, const float* __restrict__ K,
    const float* __restrict__ V, float* __restrict__ O)
{
    extern __shared__ __align__(16) uint32_t smu[];
    uint32_t* Qs = smu;               // [128][68] tf32
    uint32_t* Ks = smu + 128 * 68;    // [64][68]  tf32
    uint32_t* Vp = smu + 192 * 68;    // [32][72]  half2 (keys 2kp,2kp+1)

    const int qb   = blockIdx.x;
    const int b    = blockIdx.y >> 4;
    const int h    = blockIdx.y & 15;
    const int tid  = threadIdx.x;
    const int w    = tid >> 5;
    const int lane = tid & 31;
    const int li   = lane >> 2;
    const int lc   = lane & 3;
    const size_t base = ((size_t)b * SS) * DD + h * DHH;

    // Load Q tile (128 x 64), scaled, tf32
    #pragma unroll
    for (int it = 0; it < 8; it++) {
        int t   = tid + it * 256;
        int row = t >> 4, c4 = (t & 15) << 2;
        float4 qv = *(const float4*)(Q + base + (size_t)(qb * 128 + row) * DD + c4);
        uint4 u;
        u.x = f2tf(qv.x * 0.125f); u.y = f2tf(qv.y * 0.125f);
        u.z = f2tf(qv.z * 0.125f); u.w = f2tf(qv.w * 0.125f);
        *(uint4*)(Qs + row * 68 + c4) = u;
    }

    float m0 = -1e30f, m1 = -1e30f, l0 = 0.f, l1 = 0.f;
    float o[8][4];
    #pragma unroll
    for (int ot = 0; ot < 8; ot++)
        #pragma unroll
        for (int r = 0; r < 4; r++) o[ot][r] = 0.f;

    const int qlo = qb * 128 + w * 16;   // warp's first query row
    const int nkv = 2 * qb + 2;

    for (int kb = 0; kb < nkv; kb++) {
        __syncthreads();   // prev iter's smem reads done (Q load on iter 0)

        // K tile (64 x 64) -> tf32
        #pragma unroll
        for (int it = 0; it < 4; it++) {
            int t   = tid + it * 256;
            int row = t >> 4, c4 = (t & 15) << 2;
            float4 kv = *(const float4*)(K + base + (size_t)(kb * 64 + row) * DD + c4);
            uint4 u;
            u.x = f2tf(kv.x); u.y = f2tf(kv.y);
            u.z = f2tf(kv.z); u.w = f2tf(kv.w);
            *(uint4*)(Ks + row * 68 + c4) = u;
        }
        // V tile -> half2 key pairs
        #pragma unroll
        for (int it = 0; it < 2; it++) {
            int t  = tid + it * 256;
            int kp = t >> 4, c4 = (t & 15) << 2;
            float4 v0 = *(const float4*)(V + base + (size_t)(kb * 64 + 2 * kp)     * DD + c4);
            float4 v1 = *(const float4*)(V + base + (size_t)(kb * 64 + 2 * kp + 1) * DD + c4);
            uint4 u;
            u.x = packh2(v0.x, v1.x); u.y = packh2(v0.y, v1.y);
            u.z = packh2(v0.z, v1.z); u.w = packh2(v0.w, v1.w);
            *(uint4*)(Vp + kp * 72 + c4) = u;
        }
        __syncthreads();

        // S = Q K^T  (8 n-tiles of m16n8, k = 64 in 8 steps)
        float s[8][4];
        #pragma unroll
        for (int nt = 0; nt < 8; nt++)
            #pragma unroll
            for (int r = 0; r < 4; r++) s[nt][r] = 0.f;

        #pragma unroll
        for (int kc = 0; kc < 8; kc++) {
            const uint32_t* qr = Qs + (w * 16 + li) * 68 + kc * 8 + lc;
            uint32_t a[4];
            a[0] = qr[0]; a[1] = qr[8 * 68]; a[2] = qr[4]; a[3] = qr[8 * 68 + 4];
            #pragma unroll
            for (int nt = 0; nt < 8; nt++) {
                const uint32_t* kr = Ks + (nt * 8 + li) * 68 + kc * 8 + lc;
                uint32_t bfr[2];
                bfr[0] = kr[0]; bfr[1] = kr[4];
                mma_tf32(s[nt], a, bfr);
            }
        }

        // causal mask (diagonal region only)
        if (kb * 64 + 63 > qlo) {
            #pragma unroll
            for (int nt = 0; nt < 8; nt++) {
                int key = kb * 64 + nt * 8 + 2 * lc;
                if (key     > qlo + li)     s[nt][0] = -1e30f;
                if (key + 1 > qlo + li)     s[nt][1] = -1e30f;
                if (key     > qlo + li + 8) s[nt][2] = -1e30f;
                if (key + 1 > qlo + li + 8) s[nt][3] = -1e30f;
            }
        }

        // online softmax (row li -> regs 0,1 ; row li+8 -> regs 2,3)
        float mx0 = -1e30f, mx1 = -1e30f;
        #pragma unroll
        for (int nt = 0; nt < 8; nt++) {
            mx0 = fmaxf(mx0, fmaxf(s[nt][0], s[nt][1]));
            mx1 = fmaxf(mx1, fmaxf(s[nt][2], s[nt][3]));
        }
        mx0 = fmaxf(mx0, __shfl_xor_sync(0xffffffffu, mx0, 1));
        mx0 = fmaxf(mx0, __shfl_xor_sync(0xffffffffu, mx0, 2));
        mx1 = fmaxf(mx1, __shfl_xor_sync(0xffffffffu, mx1, 1));
        mx1 = fmaxf(mx1, __shfl_xor_sync(0xffffffffu, mx1, 2));

        float mn0 = fmaxf(m0, mx0), mn1 = fmaxf(m1, mx1);
        float cr0 = __expf(m0 - mn0), cr1 = __expf(m1 - mn1);
        float rs0 = 0.f, rs1 = 0.f;
        #pragma unroll
        for (int nt = 0; nt < 8; nt++) {
            s[nt][0] = __expf(s[nt][0] - mn0); rs0 += s[nt][0];
            s[nt][1] = __expf(s[nt][1] - mn0); rs0 += s[nt][1];
            s[nt][2] = __expf(s[nt][2] - mn1); rs1 += s[nt][2];
            s[nt][3] = __expf(s[nt][3] - mn1); rs1 += s[nt][3];
        }
        rs0 += __shfl_xor_sync(0xffffffffu, rs0, 1);
        rs0 += __shfl_xor_sync(0xffffffffu, rs0, 2);
        rs1 += __shfl_xor_sync(0xffffffffu, rs1, 1);
        rs1 += __shfl_xor_sync(0xffffffffu, rs1, 2);
        l0 = l0 * cr0 + rs0;  l1 = l1 * cr1 + rs1;
        m0 = mn0;             m1 = mn1;
        #pragma unroll
        for (int ot = 0; ot < 8; ot++) {
            o[ot][0] *= cr0; o[ot][1] *= cr0;
            o[ot][2] *= cr1; o[ot][3] *= cr1;
        }

        // O += P V   (fp16 m16n8k16; P from S frags, zero-shuffle repack)
        #pragma unroll
        for (int j = 0; j < 4; j++) {
            uint32_t pa[4];
            pa[0] = packh2(s[2*j][0],   s[2*j][1]);
            pa[1] = packh2(s[2*j][2],   s[2*j][3]);
            pa[2] = packh2(s[2*j+1][0], s[2*j+1][1]);
            pa[3] = packh2(s[2*j+1][2], s[2*j+1][3]);
            #pragma unroll
            for (int ot = 0; ot < 8; ot++) {
                uint32_t vb[2];
                vb[0] = Vp[(j * 8 + lc)     * 72 + ot * 8 + li];
                vb[1] = Vp[(j * 8 + 4 + lc) * 72 + ot * 8 + li];
                mma_f16(o[ot], pa, vb);
            }
        }
    }

    // epilogue
    float inv0 = 1.0f / l0, inv1 = 1.0f / l1;
    #pragma unroll
    for (int ot = 0; ot < 8; ot++) {
        int cp = ot * 8 + 2 * lc;
        *(float2*)(O + base + (size_t)(qlo + li)     * DD + cp) =
            make_float2(o[ot][0] * inv0, o[ot][1] * inv0);
        *(float2*)(O + base + (size_t)(qlo + li + 8) * DD + cp) =
            make_float2(o[ot][2] * inv1, o[ot][3] * inv1);
    }
}

// ---------------------------------------------------------------------------
extern "C" void kernel_launch(void* const* d_in, const int* in_sizes, int n_in,
                              void* d_out, int out_size)
{
    const float* x  = (const float*)d_in[0];
    const float* Wq = (const float*)d_in[1];
    const float* Wk = (const float*)d_in[2];
    const float* Wv = (const float*)d_in[3];
    const float* Wo = (const float*)d_in[4];
    float* out = (float*)d_out;

    float *q, *k, *v, *ho;
    cudaGetSymbolAddress((void**)&q,  g_q);
    cudaGetSymbolAddress((void**)&k,  g_k);
    cudaGetSymbolAddress((void**)&v,  g_v);
    cudaGetSymbolAddress((void**)&ho, g_ho);

    dim3 gg(DD / 128, MTOT / 128);  // (8, 64)
    gemm_tc<<<gg, 256>>>(x, Wq, q, 1);
    gemm_tc<<<gg, 256>>>(x, Wk, k, 1);
    gemm_tc<<<gg, 256>>>(x, Wv, v, 0);

    cudaFuncSetAttribute(attn_tc,
                         cudaFuncAttributeMaxDynamicSharedMemorySize, ATT_SMEM);
    attn_tc<<<dim3(SS / 128, BB * HH), 256, ATT_SMEM>>>(q, k, v, ho);

    gemm_tc<<<gg, 256>>>(ho, Wo, out, 0);
}

// round 11
// speedup vs baseline: 3.4301x; 1.0496x over previous
#include <cuda_runtime.h>
#include <cuda_fp16.h>
#include <math.h>
#include <stdint.h>

#define BB   4
#define SS   2048
#define DD   1024
#define HH   16
#define DHH  64
#define MTOT (BB*SS)

// Scratch (allocation-free rule: __device__ globals)
__device__ float g_q [MTOT*DD];
__device__ float g_k [MTOT*DD];
__device__ float g_v [MTOT*DD];
__device__ float g_ho[MTOT*DD];

// ---------------------------------------------------------------------------
// mma helpers
// ---------------------------------------------------------------------------
__device__ __forceinline__ uint32_t f2tf(float x) {
    uint32_t u;
    asm("cvt.rna.tf32.f32 %0, %1;" : "=r"(u) : "f"(x));
    return u;
}

__device__ __forceinline__ void mma_tf32(float* c, const uint32_t* a, const uint32_t* b) {
    asm volatile(
        "mma.sync.aligned.m16n8k8.row.col.f32.tf32.tf32.f32 "
        "{%0,%1,%2,%3}, {%4,%5,%6,%7}, {%8,%9}, {%0,%1,%2,%3};"
        : "+f"(c[0]), "+f"(c[1]), "+f"(c[2]), "+f"(c[3])
        : "r"(a[0]), "r"(a[1]), "r"(a[2]), "r"(a[3]),
          "r"(b[0]), "r"(b[1]));
}

__device__ __forceinline__ void mma_f16(float* c, const uint32_t* a, const uint32_t* b) {
    asm volatile(
        "mma.sync.aligned.m16n8k16.row.col.f32.f16.f16.f32 "
        "{%0,%1,%2,%3}, {%4,%5,%6,%7}, {%8,%9}, {%0,%1,%2,%3};"
        : "+f"(c[0]), "+f"(c[1]), "+f"(c[2]), "+f"(c[3])
        : "r"(a[0]), "r"(a[1]), "r"(a[2]), "r"(a[3]),
          "r"(b[0]), "r"(b[1]));
}

__device__ __forceinline__ uint32_t packh2(float lo, float hi) {
    __half2 h = __floats2half2_rn(lo, hi);
    return *(uint32_t*)&h;
}

// ---------------------------------------------------------------------------
// NT GEMM via fp16 tensor cores (fp32 accumulate): C[m,n] = sum_k A[m,k]*W[n,k]
// fp16 mantissa == tf32 mantissa (11 bits) -> same accuracy, 2x HMMA rate.
// Block 128x128x32, 256 threads (8 warps 2m x 4n), warp 64x32,
// mma m16n8k16 (4x4 tiles x 2 k-steps).
// Smem: half2 k-pair words, [row][kp] stride 16, swizzle kp ^= ((row>>1)&3)<<2
//   -> STS128 writer 8 distinct banks/phase, fragment LDS32 conflict-free.
// Register prefetch overlaps LDG of next K-tile with MMA of current one.
// applyRope: RoPE fused in epilogue (C frag cols are (even,odd) pairs).
// ---------------------------------------------------------------------------
__global__ __launch_bounds__(256, 1) void gemm_tc(
    const float* __restrict__ A, const float* __restrict__ W,
    float* __restrict__ C, int applyRope)
{
    __shared__ __align__(16) uint32_t As[128 * 16];
    __shared__ __align__(16) uint32_t Bs[128 * 16];

    const int tid  = threadIdx.x;
    const int bm   = blockIdx.y * 128;
    const int bn   = blockIdx.x * 128;
    const int wid  = tid >> 5;
    const int lane = tid & 31;
    const int wm   = wid >> 2;      // 0..1
    const int wn   = wid & 3;       // 0..3
    const int li   = lane >> 2;     // 0..7
    const int lc   = lane & 3;      // 0..3

    // writer: thread covers row (tid>>1), k-half h = tid&1 (16 floats = 8 kp)
    const int row = tid >> 1;
    const int h   = tid & 1;
    const int sww = ((row >> 1) & 3) << 2;      // writer swizzle
    const int swr = ((li  >> 1) & 3) << 2;      // reader swizzle

    const float4* Ag = (const float4*)(A + (size_t)(bm + row) * DD) + h * 4;
    const float4* Bg = (const float4*)(W + (size_t)(bn + row) * DD) + h * 4;

    float acc[4][4][4];
    #pragma unroll
    for (int mt = 0; mt < 4; mt++)
        #pragma unroll
        for (int nt = 0; nt < 4; nt++)
            #pragma unroll
            for (int r = 0; r < 4; r++) acc[mt][nt][r] = 0.f;

    // prefetch K-tile 0 (4 float4 per matrix = 16 floats)
    float4 pa[4], pb[4];
    #pragma unroll
    for (int it = 0; it < 4; it++) {
        pa[it] = Ag[it];
        pb[it] = Bg[it];
    }

    for (int kt0 = 0; kt0 < 32; kt0++) {
        // pack to half2 + store (two swizzled uint4 per matrix)
        {
            uint4 wa0, wa1, wb0, wb1;
            wa0.x = packh2(pa[0].x, pa[0].y); wa0.y = packh2(pa[0].z, pa[0].w);
            wa0.z = packh2(pa[1].x, pa[1].y); wa0.w = packh2(pa[1].z, pa[1].w);
            wa1.x = packh2(pa[2].x, pa[2].y); wa1.y = packh2(pa[2].z, pa[2].w);
            wa1.z = packh2(pa[3].x, pa[3].y); wa1.w = packh2(pa[3].z, pa[3].w);
            wb0.x = packh2(pb[0].x, pb[0].y); wb0.y = packh2(pb[0].z, pb[0].w);
            wb0.z = packh2(pb[1].x, pb[1].y); wb0.w = packh2(pb[1].z, pb[1].w);
            wb1.x = packh2(pb[2].x, pb[2].y); wb1.y = packh2(pb[2].z, pb[2].w);
            wb1.z = packh2(pb[3].x, pb[3].y); wb1.w = packh2(pb[3].z, pb[3].w);
            int i0 = row * 16 + ((h * 8)     ^ sww);
            int i1 = row * 16 + ((h * 8 + 4) ^ sww);
            *(uint4*)(As + i0) = wa0;
            *(uint4*)(As + i1) = wa1;
            *(uint4*)(Bs + i0) = wb0;
            *(uint4*)(Bs + i1) = wb1;
        }
        __syncthreads();

        // prefetch next K-tile
        if (kt0 < 31) {
            #pragma unroll
            for (int it = 0; it < 4; it++) {
                pa[it] = Ag[(kt0 + 1) * 8 + it];
                pb[it] = Bg[(kt0 + 1) * 8 + it];
            }
        }

        // 2 k16 steps
        #pragma unroll
        for (int kt = 0; kt < 2; kt++) {
            const int kpA = (kt * 8 + lc)     ^ swr;
            const int kpB = (kt * 8 + lc + 4) ^ swr;

            uint32_t af[4][4];
            #pragma unroll
            for (int mt = 0; mt < 4; mt++) {
                int ra = wm * 64 + mt * 16 + li;
                af[mt][0] = As[ra * 16 + kpA];
                af[mt][1] = As[(ra + 8) * 16 + kpA];
                af[mt][2] = As[ra * 16 + kpB];
                af[mt][3] = As[(ra + 8) * 16 + kpB];
            }
            uint32_t bf[4][2];
            #pragma unroll
            for (int nt = 0; nt < 4; nt++) {
                int n = wn * 32 + nt * 8 + li;
                bf[nt][0] = Bs[n * 16 + kpA];
                bf[nt][1] = Bs[n * 16 + kpB];
            }
            #pragma unroll
            for (int mt = 0; mt < 4; mt++)
                #pragma unroll
                for (int nt = 0; nt < 4; nt++)
                    mma_f16(acc[mt][nt], af[mt], bf[nt]);
        }
        __syncthreads();
    }

    // epilogue (+ fused RoPE on (even,odd) column pairs)
    #pragma unroll
    for (int mt = 0; mt < 4; mt++) {
        int rg = bm + wm * 64 + mt * 16 + li;
        #pragma unroll
        for (int nt = 0; nt < 4; nt++) {
            int cp = bn + wn * 32 + nt * 8 + lc * 2;
            float c0 = acc[mt][nt][0], c1 = acc[mt][nt][1];
            float c2 = acc[mt][nt][2], c3 = acc[mt][nt][3];
            if (applyRope) {
                int   d    = cp & (DHH - 1);
                float freq = powf(10000.0f, -(float)d * (1.0f / 64.0f));
                float s0, co0, s1, co1;
                sincosf((float)(rg & (SS - 1)) * freq, &s0, &co0);
                sincosf((float)((rg + 8) & (SS - 1)) * freq, &s1, &co1);
                float t;
                t  = c0 * co0 - c1 * s0;  c1 = c0 * s0 + c1 * co0;  c0 = t;
                t  = c2 * co1 - c3 * s1;  c3 = c2 * s1 + c3 * co1;  c2 = t;
            }
            *(float2*)(C + (size_t)rg * DD + cp)       = make_float2(c0, c1);
            *(float2*)(C + (size_t)(rg + 8) * DD + cp) = make_float2(c2, c3);
        }
    }
}

// ---------------------------------------------------------------------------
// Tensor-core causal flash attention (unchanged, known-correct from R9 bench).
// ---------------------------------------------------------------------------
#define ATT_SMEM (128*68*4 + 64*68*4 + 32*72*4)   // 61440 B

__global__ __launch_bounds__(256, 1) void attn_tc(
    const float* __restrict__ Q, const float* __restrict__ K,
    const float* __restrict__ V, float* __restrict__ O)
{
    extern __shared__ __align__(16) uint32_t smu[];
    uint32_t* Qs = smu;               // [128][68] tf32
    uint32_t* Ks = smu + 128 * 68;    // [64][68]  tf32
    uint32_t* Vp = smu + 192 * 68;    // [32][72]  half2 (keys 2kp,2kp+1)

    const int qb   = blockIdx.x;
    const int b    = blockIdx.y >> 4;
    const int h    = blockIdx.y & 15;
    const int tid  = threadIdx.x;
    const int w    = tid >> 5;
    const int lane = tid & 31;
    const int li   = lane >> 2;
    const int lc   = lane & 3;
    const size_t base = ((size_t)b * SS) * DD + h * DHH;

    #pragma unroll
    for (int it = 0; it < 8; it++) {
        int t   = tid + it * 256;
        int row = t >> 4, c4 = (t & 15) << 2;
        float4 qv = *(const float4*)(Q + base + (size_t)(qb * 128 + row) * DD + c4);
        uint4 u;
        u.x = f2tf(qv.x * 0.125f); u.y = f2tf(qv.y * 0.125f);
        u.z = f2tf(qv.z * 0.125f); u.w = f2tf(qv.w * 0.125f);
        *(uint4*)(Qs + row * 68 + c4) = u;
    }

    float m0 = -1e30f, m1 = -1e30f, l0 = 0.f, l1 = 0.f;
    float o[8][4];
    #pragma unroll
    for (int ot = 0; ot < 8; ot++)
        #pragma unroll
        for (int r = 0; r < 4; r++) o[ot][r] = 0.f;

    const int qlo = qb * 128 + w * 16;
    const int nkv = 2 * qb + 2;

    for (int kb = 0; kb < nkv; kb++) {
        __syncthreads();

        #pragma unroll
        for (int it = 0; it < 4; it++) {
            int t   = tid + it * 256;
            int row = t >> 4, c4 = (t & 15) << 2;
            float4 kv = *(const float4*)(K + base + (size_t)(kb * 64 + row) * DD + c4);
            uint4 u;
            u.x = f2tf(kv.x); u.y = f2tf(kv.y);
            u.z = f2tf(kv.z); u.w = f2tf(kv.w);
            *(uint4*)(Ks + row * 68 + c4) = u;
        }
        #pragma unroll
        for (int it = 0; it < 2; it++) {
            int t  = tid + it * 256;
            int kp = t >> 4, c4 = (t & 15) << 2;
            float4 v0 = *(const float4*)(V + base + (size_t)(kb * 64 + 2 * kp)     * DD + c4);
            float4 v1 = *(const float4*)(V + base + (size_t)(kb * 64 + 2 * kp + 1) * DD + c4);
            uint4 u;
            u.x = packh2(v0.x, v1.x); u.y = packh2(v0.y, v1.y);
            u.z = packh2(v0.z, v1.z); u.w = packh2(v0.w, v1.w);
            *(uint4*)(Vp + kp * 72 + c4) = u;
        }
        __syncthreads();

        float s[8][4];
        #pragma unroll
        for (int nt = 0; nt < 8; nt++)
            #pragma unroll
            for (int r = 0; r < 4; r++) s[nt][r] = 0.f;

        #pragma unroll
        for (int kc = 0; kc < 8; kc++) {
            const uint32_t* qr = Qs + (w * 16 + li) * 68 + kc * 8 + lc;
            uint32_t a[4];
            a[0] = qr[0]; a[1] = qr[8 * 68]; a[2] = qr[4]; a[3] = qr[8 * 68 + 4];
            #pragma unroll
            for (int nt = 0; nt < 8; nt++) {
                const uint32_t* kr = Ks + (nt * 8 + li) * 68 + kc * 8 + lc;
                uint32_t bfr[2];
                bfr[0] = kr[0]; bfr[1] = kr[4];
                mma_tf32(s[nt], a, bfr);
            }
        }

        if (kb * 64 + 63 > qlo) {
            #pragma unroll
            for (int nt = 0; nt < 8; nt++) {
                int key = kb * 64 + nt * 8 + 2 * lc;
                if (key     > qlo + li)     s[nt][0] = -1e30f;
                if (key + 1 > qlo + li)     s[nt][1] = -1e30f;
                if (key     > qlo + li + 8) s[nt][2] = -1e30f;
                if (key + 1 > qlo + li + 8) s[nt][3] = -1e30f;
            }
        }

        float mx0 = -1e30f, mx1 = -1e30f;
        #pragma unroll
        for (int nt = 0; nt < 8; nt++) {
            mx0 = fmaxf(mx0, fmaxf(s[nt][0], s[nt][1]));
            mx1 = fmaxf(mx1, fmaxf(s[nt][2], s[nt][3]));
        }
        mx0 = fmaxf(mx0, __shfl_xor_sync(0xffffffffu, mx0, 1));
        mx0 = fmaxf(mx0, __shfl_xor_sync(0xffffffffu, mx0, 2));
        mx1 = fmaxf(mx1, __shfl_xor_sync(0xffffffffu, mx1, 1));
        mx1 = fmaxf(mx1, __shfl_xor_sync(0xffffffffu, mx1, 2));

        float mn0 = fmaxf(m0, mx0), mn1 = fmaxf(m1, mx1);
        float cr0 = __expf(m0 - mn0), cr1 = __expf(m1 - mn1);
        float rs0 = 0.f, rs1 = 0.f;
        #pragma unroll
        for (int nt = 0; nt < 8; nt++) {
            s[nt][0] = __expf(s[nt][0] - mn0); rs0 += s[nt][0];
            s[nt][1] = __expf(s[nt][1] - mn0); rs0 += s[nt][1];
            s[nt][2] = __expf(s[nt][2] - mn1); rs1 += s[nt][2];
            s[nt][3] = __expf(s[nt][3] - mn1); rs1 += s[nt][3];
        }
        rs0 += __shfl_xor_sync(0xffffffffu, rs0, 1);
        rs0 += __shfl_xor_sync(0xffffffffu, rs0, 2);
        rs1 += __shfl_xor_sync(0xffffffffu, rs1, 1);
        rs1 += __shfl_xor_sync(0xffffffffu, rs1, 2);
        l0 = l0 * cr0 + rs0;  l1 = l1 * cr1 + rs1;
        m0 = mn0;             m1 = mn1;
        #pragma unroll
        for (int ot = 0; ot < 8; ot++) {
            o[ot][0] *= cr0; o[ot][1] *= cr0;
            o[ot][2] *= cr1; o[ot][3] *= cr1;
        }

        #pragma unroll
        for (int j = 0; j < 4; j++) {
            uint32_t pa[4];
            pa[0] = packh2(s[2*j][0],   s[2*j][1]);
            pa[1] = packh2(s[2*j][2],   s[2*j][3]);
            pa[2] = packh2(s[2*j+1][0], s[2*j+1][1]);
            pa[3] = packh2(s[2*j+1][2], s[2*j+1][3]);
            #pragma unroll
            for (int ot = 0; ot < 8; ot++) {
                uint32_t vb[2];
                vb[0] = Vp[(j * 8 + lc)     * 72 + ot * 8 + li];
                vb[1] = Vp[(j * 8 + 4 + lc) * 72 + ot * 8 + li];
                mma_f16(o[ot], pa, vb);
            }
        }
    }

    float inv0 = 1.0f / l0, inv1 = 1.0f / l1;
    #pragma unroll
    for (int ot = 0; ot < 8; ot++) {
        int cp = ot * 8 + 2 * lc;
        *(float2*)(O + base + (size_t)(qlo + li)     * DD + cp) =
            make_float2(o[ot][0] * inv0, o[ot][1] * inv0);
        *(float2*)(O + base + (size_t)(qlo + li + 8) * DD + cp) =
            make_float2(o[ot][2] * inv1, o[ot][3] * inv1);
    }
}

// ---------------------------------------------------------------------------
extern "C" void kernel_launch(void* const* d_in, const int* in_sizes, int n_in,
                              void* d_out, int out_size)
{
    const float* x  = (const float*)d_in[0];
    const float* Wq = (const float*)d_in[1];
    const float* Wk = (const float*)d_in[2];
    const float* Wv = (const float*)d_in[3];
    const float* Wo = (const float*)d_in[4];
    float* out = (float*)d_out;

    float *q, *k, *v, *ho;
    cudaGetSymbolAddress((void**)&q,  g_q);
    cudaGetSymbolAddress((void**)&k,  g_k);
    cudaGetSymbolAddress((void**)&v,  g_v);
    cudaGetSymbolAddress((void**)&ho, g_ho);

    dim3 gg(DD / 128, MTOT / 128);  // (8, 64)
    gemm_tc<<<gg, 256>>>(x, Wq, q, 1);
    gemm_tc<<<gg, 256>>>(x, Wk, k, 1);
    gemm_tc<<<gg, 256>>>(x, Wv, v, 0);

    cudaFuncSetAttribute(attn_tc,
                         cudaFuncAttributeMaxDynamicSharedMemorySize, ATT_SMEM);
    attn_tc<<<dim3(SS / 128, BB * HH), 256, ATT_SMEM>>>(q, k, v, ho);

    gemm_tc<<<gg, 256>>>(ho, Wo, out, 0);
}

// round 12
// speedup vs baseline: 5.3559x; 1.5614x over previous
#include <cuda_runtime.h>
#include <cuda_fp16.h>
#include <math.h>
#include <stdint.h>

#define BB   4
#define SS   2048
#define DD   1024
#define HH   16
#define DHH  64
#define MTOT (BB*SS)

// Scratch (allocation-free rule: __device__ globals)
__device__ float  g_q  [MTOT*DD];
__device__ float  g_k  [MTOT*DD];
__device__ float  g_v  [MTOT*DD];
__device__ float  g_ho [MTOT*DD];
__device__ __half g_xh [MTOT*DD];
__device__ __half g_hoh[MTOT*DD];
__device__ __half g_wqh[DD*DD];
__device__ __half g_wkh[DD*DD];
__device__ __half g_wvh[DD*DD];
__device__ __half g_woh[DD*DD];

// ---------------------------------------------------------------------------
// helpers
// ---------------------------------------------------------------------------
__device__ __forceinline__ uint32_t f2tf(float x) {
    uint32_t u;
    asm("cvt.rna.tf32.f32 %0, %1;" : "=r"(u) : "f"(x));
    return u;
}

__device__ __forceinline__ void mma_tf32(float* c, const uint32_t* a, const uint32_t* b) {
    asm volatile(
        "mma.sync.aligned.m16n8k8.row.col.f32.tf32.tf32.f32 "
        "{%0,%1,%2,%3}, {%4,%5,%6,%7}, {%8,%9}, {%0,%1,%2,%3};"
        : "+f"(c[0]), "+f"(c[1]), "+f"(c[2]), "+f"(c[3])
        : "r"(a[0]), "r"(a[1]), "r"(a[2]), "r"(a[3]),
          "r"(b[0]), "r"(b[1]));
}

__device__ __forceinline__ void mma_f16(float* c, const uint32_t* a, const uint32_t* b) {
    asm volatile(
        "mma.sync.aligned.m16n8k16.row.col.f32.f16.f16.f32 "
        "{%0,%1,%2,%3}, {%4,%5,%6,%7}, {%8,%9}, {%0,%1,%2,%3};"
        : "+f"(c[0]), "+f"(c[1]), "+f"(c[2]), "+f"(c[3])
        : "r"(a[0]), "r"(a[1]), "r"(a[2]), "r"(a[3]),
          "r"(b[0]), "r"(b[1]));
}

__device__ __forceinline__ uint32_t packh2(float lo, float hi) {
    __half2 h = __floats2half2_rn(lo, hi);
    return *(uint32_t*)&h;
}

__device__ __forceinline__ uint32_t smem_u32(const void* p) {
    return (uint32_t)__cvta_generic_to_shared(p);
}

#define CP16(dst, src) \
    asm volatile("cp.async.cg.shared.global [%0], [%1], 16;" :: "r"(dst), "l"(src))
#define CPCOMMIT() asm volatile("cp.async.commit_group;")
#define CPWAIT2()  asm volatile("cp.async.wait_group 2;")

#define LDSM4(r0, r1, r2, r3, addr) \
    asm volatile("ldmatrix.sync.aligned.m8n8.x4.shared.b16 {%0,%1,%2,%3}, [%4];" \
                 : "=r"(r0), "=r"(r1), "=r"(r2), "=r"(r3) : "r"(addr))

// ---------------------------------------------------------------------------
// fp32 -> fp16 elementwise convert (8 elems/thread)
// ---------------------------------------------------------------------------
__global__ void f2h_kernel(const float* __restrict__ in, __half* __restrict__ out, int n)
{
    int i = (blockIdx.x * blockDim.x + threadIdx.x) << 3;
    if (i >= n) return;
    float4 v0 = *(const float4*)(in + i);
    float4 v1 = *(const float4*)(in + i + 4);
    __half2 h[4];
    h[0] = __floats2half2_rn(v0.x, v0.y);
    h[1] = __floats2half2_rn(v0.z, v0.w);
    h[2] = __floats2half2_rn(v1.x, v1.y);
    h[3] = __floats2half2_rn(v1.z, v1.w);
    *(uint4*)(out + i) = *(uint4*)h;
}

// ---------------------------------------------------------------------------
// NT GEMM, fp16 inputs, fp32 accumulate: C[m,n] = sum_k A[m,k] * W[n,k]
// Block 128x128x32, 256 threads (8 warps 2m x 4n), warp 64x32, mma m16n8k16.
// 4-stage cp.async pipeline (3 tiles in flight), ldmatrix.x4 fragments.
// Smem [stage][row][k 32 halves]; 16B-chunk swizzle: c ^= (r&3)^((r>>2)&1)
//   (conflict-free for cp.async store phases and all LDSM read phases).
// applyRope: RoPE fused in epilogue.
// ---------------------------------------------------------------------------
#define GST     (128 * 32)                 // halves per stage per matrix
#define GSTAGES 4
#define GEMM_SMEM (GSTAGES * GST * 2 * 2)  // 65536 B

__global__ __launch_bounds__(256, 2) void gemm_h(
    const __half* __restrict__ A, const __half* __restrict__ W,
    float* __restrict__ C, int applyRope)
{
    extern __shared__ __align__(16) __half hs[];
    __half* As = hs;                   // [4][128][32]
    __half* Bs = hs + GSTAGES * GST;

    const int tid  = threadIdx.x;
    const int bm   = blockIdx.y * 128;
    const int bn   = blockIdx.x * 128;
    const int wid  = tid >> 5;
    const int lane = tid & 31;
    const int wm   = wid >> 2;      // 0..1
    const int wn   = wid & 3;       // 0..3
    const int li   = lane >> 2;
    const int lc   = lane & 3;

    // ---- cp.async writer mapping: row = tid>>1, chunk pair = (tid&1)*2 ----
    const int row = tid >> 1;
    const int cp2 = (tid & 1) * 2;
    const int sws = ((row & 3) ^ ((row >> 2) & 1));
    const uint32_t d0b = (uint32_t)(row * 32 + ((cp2    ) ^ sws) * 8) * 2;
    const uint32_t d1b = (uint32_t)(row * 32 + ((cp2 + 1) ^ sws) * 8) * 2;

    const __half* ag = A + (size_t)(bm + row) * DD + cp2 * 8;
    const __half* bg = W + (size_t)(bn + row) * DD + cp2 * 8;

    const uint32_t asA = smem_u32(As);
    const uint32_t asB = smem_u32(Bs);

#define ISSUE(t, s) do {                                    \
        uint32_t o_ = (uint32_t)(s) * (GST * 2);            \
        CP16(asA + o_ + d0b, ag + (t) * 32);                \
        CP16(asA + o_ + d1b, ag + (t) * 32 + 8);            \
        CP16(asB + o_ + d0b, bg + (t) * 32);                \
        CP16(asB + o_ + d1b, bg + (t) * 32 + 8);            \
    } while (0)

    // ---- ldmatrix reader mapping ----
    const int swf    = ((lane & 3) ^ ((lane >> 2) & 1));
    const int laneAr = wm * 64 + (lane & 15);
    const int laneAc = (lane >> 4);            // 0/1 (k chunk within k16)
    const int laneBr = wn * 32 + ((lane & 16) >> 1) + (lane & 7);
    const int laneBc = ((lane >> 3) & 1);

    float acc[4][4][4];
    #pragma unroll
    for (int mt = 0; mt < 4; mt++)
        #pragma unroll
        for (int nt = 0; nt < 4; nt++)
            #pragma unroll
            for (int r = 0; r < 4; r++) acc[mt][nt][r] = 0.f;

    // preload 3 tiles
    ISSUE(0, 0); CPCOMMIT();
    ISSUE(1, 1); CPCOMMIT();
    ISSUE(2, 2); CPCOMMIT();

    for (int kt = 0; kt < 32; kt++) {
        const int s = kt & 3;
        CPWAIT2();
        __syncthreads();
        if (kt + 3 < 32) ISSUE(kt + 3, (kt + 3) & 3);
        CPCOMMIT();

        const uint32_t baseA = asA + (uint32_t)s * (GST * 2);
        const uint32_t baseB = asB + (uint32_t)s * (GST * 2);

        #pragma unroll
        for (int kc = 0; kc < 2; kc++) {
            uint32_t af[4][4], bf[2][4];
            #pragma unroll
            for (int mt = 0; mt < 4; mt++) {
                uint32_t ad = baseA +
                    (uint32_t)(((laneAr + mt * 16) * 32 +
                                (((kc * 2 + laneAc) ^ swf) * 8)) * 2);
                LDSM4(af[mt][0], af[mt][1], af[mt][2], af[mt][3], ad);
            }
            #pragma unroll
            for (int ntp = 0; ntp < 2; ntp++) {
                uint32_t bd = baseB +
                    (uint32_t)(((laneBr + ntp * 16) * 32 +
                                (((kc * 2 + laneBc) ^ swf) * 8)) * 2);
                LDSM4(bf[ntp][0], bf[ntp][1], bf[ntp][2], bf[ntp][3], bd);
            }
            #pragma unroll
            for (int mt = 0; mt < 4; mt++)
                #pragma unroll
                for (int ntp = 0; ntp < 2; ntp++) {
                    mma_f16(acc[mt][ntp * 2 + 0], af[mt], &bf[ntp][0]);
                    mma_f16(acc[mt][ntp * 2 + 1], af[mt], &bf[ntp][2]);
                }
        }
    }
#undef ISSUE

    // epilogue (+ fused RoPE on (even,odd) column pairs)
    #pragma unroll
    for (int mt = 0; mt < 4; mt++) {
        int rg = bm + wm * 64 + mt * 16 + li;
        #pragma unroll
        for (int nt = 0; nt < 4; nt++) {
            int cp = bn + wn * 32 + nt * 8 + lc * 2;
            float c0 = acc[mt][nt][0], c1 = acc[mt][nt][1];
            float c2 = acc[mt][nt][2], c3 = acc[mt][nt][3];
            if (applyRope) {
                int   d    = cp & (DHH - 1);
                float freq = powf(10000.0f, -(float)d * (1.0f / 64.0f));
                float s0, co0, s1, co1;
                sincosf((float)(rg & (SS - 1)) * freq, &s0, &co0);
                sincosf((float)((rg + 8) & (SS - 1)) * freq, &s1, &co1);
                float t;
                t  = c0 * co0 - c1 * s0;  c1 = c0 * s0 + c1 * co0;  c0 = t;
                t  = c2 * co1 - c3 * s1;  c3 = c2 * s1 + c3 * co1;  c2 = t;
            }
            *(float2*)(C + (size_t)rg * DD + cp)       = make_float2(c0, c1);
            *(float2*)(C + (size_t)(rg + 8) * DD + cp) = make_float2(c2, c3);
        }
    }
}

// ---------------------------------------------------------------------------
// Tensor-core causal flash attention (unchanged, known-correct since R9).
// ---------------------------------------------------------------------------
#define ATT_SMEM (128*68*4 + 64*68*4 + 32*72*4)   // 61440 B

__global__ __launch_bounds__(256, 1) void attn_tc(
    const float* __restrict__ Q, const float* __restrict__ K,
    const float* __restrict__ V, float* __restrict__ O)
{
    extern __shared__ __align__(16) uint32_t smu[];
    uint32_t* Qs = smu;               // [128][68] tf32
    uint32_t* Ks = smu + 128 * 68;    // [64][68]  tf32
    uint32_t* Vp = smu + 192 * 68;    // [32][72]  half2 (keys 2kp,2kp+1)

    const int qb   = blockIdx.x;
    const int b    = blockIdx.y >> 4;
    const int h    = blockIdx.y & 15;
    const int tid  = threadIdx.x;
    const int w    = tid >> 5;
    const int lane = tid & 31;
    const int li   = lane >> 2;
    const int lc   = lane & 3;
    const size_t base = ((size_t)b * SS) * DD + h * DHH;

    #pragma unroll
    for (int it = 0; it < 8; it++) {
        int t   = tid + it * 256;
        int row = t >> 4, c4 = (t & 15) << 2;
        float4 qv = *(const float4*)(Q + base + (size_t)(qb * 128 + row) * DD + c4);
        uint4 u;
        u.x = f2tf(qv.x * 0.125f); u.y = f2tf(qv.y * 0.125f);
        u.z = f2tf(qv.z * 0.125f); u.w = f2tf(qv.w * 0.125f);
        *(uint4*)(Qs + row * 68 + c4) = u;
    }

    float m0 = -1e30f, m1 = -1e30f, l0 = 0.f, l1 = 0.f;
    float o[8][4];
    #pragma unroll
    for (int ot = 0; ot < 8; ot++)
        #pragma unroll
        for (int r = 0; r < 4; r++) o[ot][r] = 0.f;

    const int qlo = qb * 128 + w * 16;
    const int nkv = 2 * qb + 2;

    for (int kb = 0; kb < nkv; kb++) {
        __syncthreads();

        #pragma unroll
        for (int it = 0; it < 4; it++) {
            int t   = tid + it * 256;
            int row = t >> 4, c4 = (t & 15) << 2;
            float4 kv = *(const float4*)(K + base + (size_t)(kb * 64 + row) * DD + c4);
            uint4 u;
            u.x = f2tf(kv.x); u.y = f2tf(kv.y);
            u.z = f2tf(kv.z); u.w = f2tf(kv.w);
            *(uint4*)(Ks + row * 68 + c4) = u;
        }
        #pragma unroll
        for (int it = 0; it < 2; it++) {
            int t  = tid + it * 256;
            int kp = t >> 4, c4 = (t & 15) << 2;
            float4 v0 = *(const float4*)(V + base + (size_t)(kb * 64 + 2 * kp)     * DD + c4);
            float4 v1 = *(const float4*)(V + base + (size_t)(kb * 64 + 2 * kp + 1) * DD + c4);
            uint4 u;
            u.x = packh2(v0.x, v1.x); u.y = packh2(v0.y, v1.y);
            u.z = packh2(v0.z, v1.z); u.w = packh2(v0.w, v1.w);
            *(uint4*)(Vp + kp * 72 + c4) = u;
        }
        __syncthreads();

        float s[8][4];
        #pragma unroll
        for (int nt = 0; nt < 8; nt++)
            #pragma unroll
            for (int r = 0; r < 4; r++) s[nt][r] = 0.f;

        #pragma unroll
        for (int kc = 0; kc < 8; kc++) {
            const uint32_t* qr = Qs + (w * 16 + li) * 68 + kc * 8 + lc;
            uint32_t a[4];
            a[0] = qr[0]; a[1] = qr[8 * 68]; a[2] = qr[4]; a[3] = qr[8 * 68 + 4];
            #pragma unroll
            for (int nt = 0; nt < 8; nt++) {
                const uint32_t* kr = Ks + (nt * 8 + li) * 68 + kc * 8 + lc;
                uint32_t bfr[2];
                bfr[0] = kr[0]; bfr[1] = kr[4];
                mma_tf32(s[nt], a, bfr);
            }
        }

        if (kb * 64 + 63 > qlo) {
            #pragma unroll
            for (int nt = 0; nt < 8; nt++) {
                int key = kb * 64 + nt * 8 + 2 * lc;
                if (key     > qlo + li)     s[nt][0] = -1e30f;
                if (key + 1 > qlo + li)     s[nt][1] = -1e30f;
                if (key     > qlo + li + 8) s[nt][2] = -1e30f;
                if (key + 1 > qlo + li + 8) s[nt][3] = -1e30f;
            }
        }

        float mx0 = -1e30f, mx1 = -1e30f;
        #pragma unroll
        for (int nt = 0; nt < 8; nt++) {
            mx0 = fmaxf(mx0, fmaxf(s[nt][0], s[nt][1]));
            mx1 = fmaxf(mx1, fmaxf(s[nt][2], s[nt][3]));
        }
        mx0 = fmaxf(mx0, __shfl_xor_sync(0xffffffffu, mx0, 1));
        mx0 = fmaxf(mx0, __shfl_xor_sync(0xffffffffu, mx0, 2));
        mx1 = fmaxf(mx1, __shfl_xor_sync(0xffffffffu, mx1, 1));
        mx1 = fmaxf(mx1, __shfl_xor_sync(0xffffffffu, mx1, 2));

        float mn0 = fmaxf(m0, mx0), mn1 = fmaxf(m1, mx1);
        float cr0 = __expf(m0 - mn0), cr1 = __expf(m1 - mn1);
        float rs0 = 0.f, rs1 = 0.f;
        #pragma unroll
        for (int nt = 0; nt < 8; nt++) {
            s[nt][0] = __expf(s[nt][0] - mn0); rs0 += s[nt][0];
            s[nt][1] = __expf(s[nt][1] - mn0); rs0 += s[nt][1];
            s[nt][2] = __expf(s[nt][2] - mn1); rs1 += s[nt][2];
            s[nt][3] = __expf(s[nt][3] - mn1); rs1 += s[nt][3];
        }
        rs0 += __shfl_xor_sync(0xffffffffu, rs0, 1);
        rs0 += __shfl_xor_sync(0xffffffffu, rs0, 2);
        rs1 += __shfl_xor_sync(0xffffffffu, rs1, 1);
        rs1 += __shfl_xor_sync(0xffffffffu, rs1, 2);
        l0 = l0 * cr0 + rs0;  l1 = l1 * cr1 + rs1;
        m0 = mn0;             m1 = mn1;
        #pragma unroll
        for (int ot = 0; ot < 8; ot++) {
            o[ot][0] *= cr0; o[ot][1] *= cr0;
            o[ot][2] *= cr1; o[ot][3] *= cr1;
        }

        #pragma unroll
        for (int j = 0; j < 4; j++) {
            uint32_t pa[4];
            pa[0] = packh2(s[2*j][0],   s[2*j][1]);
            pa[1] = packh2(s[2*j][2],   s[2*j][3]);
            pa[2] = packh2(s[2*j+1][0], s[2*j+1][1]);
            pa[3] = packh2(s[2*j+1][2], s[2*j+1][3]);
            #pragma unroll
            for (int ot = 0; ot < 8; ot++) {
                uint32_t vb[2];
                vb[0] = Vp[(j * 8 + lc)     * 72 + ot * 8 + li];
                vb[1] = Vp[(j * 8 + 4 + lc) * 72 + ot * 8 + li];
                mma_f16(o[ot], pa, vb);
            }
        }
    }

    float inv0 = 1.0f / l0, inv1 = 1.0f / l1;
    #pragma unroll
    for (int ot = 0; ot < 8; ot++) {
        int cp = ot * 8 + 2 * lc;
        *(float2*)(O + base + (size_t)(qlo + li)     * DD + cp) =
            make_float2(o[ot][0] * inv0, o[ot][1] * inv0);
        *(float2*)(O + base + (size_t)(qlo + li + 8) * DD + cp) =
            make_float2(o[ot][2] * inv1, o[ot][3] * inv1);
    }
}

// ---------------------------------------------------------------------------
extern "C" void kernel_launch(void* const* d_in, const int* in_sizes, int n_in,
                              void* d_out, int out_size)
{
    const float* x  = (const float*)d_in[0];
    const float* Wq = (const float*)d_in[1];
    const float* Wk = (const float*)d_in[2];
    const float* Wv = (const float*)d_in[3];
    const float* Wo = (const float*)d_in[4];
    float* out = (float*)d_out;

    float  *q, *k, *v, *ho;
    __half *xh, *hoh, *wqh, *wkh, *wvh, *woh;
    cudaGetSymbolAddress((void**)&q,   g_q);
    cudaGetSymbolAddress((void**)&k,   g_k);
    cudaGetSymbolAddress((void**)&v,   g_v);
    cudaGetSymbolAddress((void**)&ho,  g_ho);
    cudaGetSymbolAddress((void**)&xh,  g_xh);
    cudaGetSymbolAddress((void**)&hoh, g_hoh);
    cudaGetSymbolAddress((void**)&wqh, g_wqh);
    cudaGetSymbolAddress((void**)&wkh, g_wkh);
    cudaGetSymbolAddress((void**)&wvh, g_wvh);
    cudaGetSymbolAddress((void**)&woh, g_woh);

    // fp32 -> fp16 conversions
    f2h_kernel<<<(MTOT * DD / 8 + 255) / 256, 256>>>(x,  xh,  MTOT * DD);
    f2h_kernel<<<(DD * DD / 8 + 255) / 256, 256>>>(Wq, wqh, DD * DD);
    f2h_kernel<<<(DD * DD / 8 + 255) / 256, 256>>>(Wk, wkh, DD * DD);
    f2h_kernel<<<(DD * DD / 8 + 255) / 256, 256>>>(Wv, wvh, DD * DD);
    f2h_kernel<<<(DD * DD / 8 + 255) / 256, 256>>>(Wo, woh, DD * DD);

    cudaFuncSetAttribute(gemm_h,
                         cudaFuncAttributeMaxDynamicSharedMemorySize, GEMM_SMEM);

    dim3 gg(DD / 128, MTOT / 128);  // (8, 64)
    gemm_h<<<gg, 256, GEMM_SMEM>>>(xh, wqh, q, 1);
    gemm_h<<<gg, 256, GEMM_SMEM>>>(xh, wkh, k, 1);
    gemm_h<<<gg, 256, GEMM_SMEM>>>(xh, wvh, v, 0);

    cudaFuncSetAttribute(attn_tc,
                         cudaFuncAttributeMaxDynamicSharedMemorySize, ATT_SMEM);
    attn_tc<<<dim3(SS / 128, BB * HH), 256, ATT_SMEM>>>(q, k, v, ho);

    f2h_kernel<<<(MTOT * DD / 8 + 255) / 256, 256>>>(ho, hoh, MTOT * DD);
    gemm_h<<<gg, 256, GEMM_SMEM>>>(hoh, woh, out, 0);
}

// round 15
// speedup vs baseline: 7.1433x; 1.3337x over previous
#include <cuda_runtime.h>
#include <cuda_fp16.h>
#include <math.h>
#include <stdint.h>

#define BB   4
#define SS   2048
#define DD   1024
#define HH   16
#define DHH  64
#define MTOT (BB*SS)

// Scratch (allocation-free rule: __device__ globals)
__device__ __half g_qh [MTOT*DD];
__device__ __half g_kh [MTOT*DD];
__device__ __half g_vh [MTOT*DD];
__device__ __half g_hoh[MTOT*DD];
__device__ __half g_xh [MTOT*DD];
__device__ __half g_wqh[DD*DD];
__device__ __half g_wkh[DD*DD];
__device__ __half g_wvh[DD*DD];
__device__ __half g_woh[DD*DD];

// ---------------------------------------------------------------------------
// helpers
// ---------------------------------------------------------------------------
__device__ __forceinline__ void mma_f16(float* c, const uint32_t* a, const uint32_t* b) {
    asm volatile(
        "mma.sync.aligned.m16n8k16.row.col.f32.f16.f16.f32 "
        "{%0,%1,%2,%3}, {%4,%5,%6,%7}, {%8,%9}, {%0,%1,%2,%3};"
        : "+f"(c[0]), "+f"(c[1]), "+f"(c[2]), "+f"(c[3])
        : "r"(a[0]), "r"(a[1]), "r"(a[2]), "r"(a[3]),
          "r"(b[0]), "r"(b[1]));
}

__device__ __forceinline__ uint32_t packh2(float lo, float hi) {
    __half2 h = __floats2half2_rn(lo, hi);
    return *(uint32_t*)&h;
}

__device__ __forceinline__ uint32_t smem_u32(const void* p) {
    return (uint32_t)__cvta_generic_to_shared(p);
}

#define CP16(dst, src) \
    asm volatile("cp.async.cg.shared.global [%0], [%1], 16;" :: "r"(dst), "l"(src))
#define CPCOMMIT() asm volatile("cp.async.commit_group;")

#define LDSM4(r0, r1, r2, r3, addr) \
    asm volatile("ldmatrix.sync.aligned.m8n8.x4.shared.b16 {%0,%1,%2,%3}, [%4];" \
                 : "=r"(r0), "=r"(r1), "=r"(r2), "=r"(r3) : "r"(addr))
#define LDSM2(r0, r1, addr) \
    asm volatile("ldmatrix.sync.aligned.m8n8.x2.shared.b16 {%0,%1}, [%2];" \
                 : "=r"(r0), "=r"(r1) : "r"(addr))
#define LDSM2T(r0, r1, addr) \
    asm volatile("ldmatrix.sync.aligned.m8n8.x2.trans.shared.b16 {%0,%1}, [%2];" \
                 : "=r"(r0), "=r"(r1) : "r"(addr))

// ---------------------------------------------------------------------------
// fp32 -> fp16 elementwise convert (8 elems/thread)
// ---------------------------------------------------------------------------
__global__ void f2h_kernel(const float* __restrict__ in, __half* __restrict__ out, int n)
{
    int i = (blockIdx.x * blockDim.x + threadIdx.x) << 3;
    if (i >= n) return;
    float4 v0 = *(const float4*)(in + i);
    float4 v1 = *(const float4*)(in + i + 4);
    __half2 h[4];
    h[0] = __floats2half2_rn(v0.x, v0.y);
    h[1] = __floats2half2_rn(v0.z, v0.w);
    h[2] = __floats2half2_rn(v1.x, v1.y);
    h[3] = __floats2half2_rn(v1.z, v1.w);
    *(uint4*)(out + i) = *(uint4*)h;
}

// ---------------------------------------------------------------------------
// NT GEMM, fp16 inputs, fp32 accumulate. HOUT: fp16 or fp32 output.
// Block 128x128x32, 256 threads, 4-stage cp.async pipeline, ldmatrix.x4.
// applyRope: RoPE fused in epilogue; oscale: output scaling (1/sqrt(dh) for Q).
// ---------------------------------------------------------------------------
#define GST     (128 * 32)
#define GSTAGES 4
#define GEMM_SMEM (GSTAGES * GST * 2 * 2)  // 65536 B

template <bool HOUT>
__global__ __launch_bounds__(256, 2) void gemm_h(
    const __half* __restrict__ A, const __half* __restrict__ W,
    void* __restrict__ Cv, int applyRope, float oscale)
{
    extern __shared__ __align__(16) __half hs[];
    __half* As = hs;
    __half* Bs = hs + GSTAGES * GST;

    const int tid  = threadIdx.x;
    const int bm   = blockIdx.y * 128;
    const int bn   = blockIdx.x * 128;
    const int wid  = tid >> 5;
    const int lane = tid & 31;
    const int wm   = wid >> 2;
    const int wn   = wid & 3;
    const int li   = lane >> 2;
    const int lc   = lane & 3;

    const int row = tid >> 1;
    const int cp2 = (tid & 1) * 2;
    const int sws = ((row & 3) ^ ((row >> 2) & 1));
    const uint32_t d0b = (uint32_t)(row * 32 + ((cp2    ) ^ sws) * 8) * 2;
    const uint32_t d1b = (uint32_t)(row * 32 + ((cp2 + 1) ^ sws) * 8) * 2;

    const __half* ag = A + (size_t)(bm + row) * DD + cp2 * 8;
    const __half* bg = W + (size_t)(bn + row) * DD + cp2 * 8;

    const uint32_t asA = smem_u32(As);
    const uint32_t asB = smem_u32(Bs);

#define ISSUE(t, s) do {                                    \
        uint32_t o_ = (uint32_t)(s) * (GST * 2);            \
        CP16(asA + o_ + d0b, ag + (t) * 32);                \
        CP16(asA + o_ + d1b, ag + (t) * 32 + 8);            \
        CP16(asB + o_ + d0b, bg + (t) * 32);                \
        CP16(asB + o_ + d1b, bg + (t) * 32 + 8);            \
    } while (0)

    const int swf    = ((lane & 3) ^ ((lane >> 2) & 1));
    const int laneAr = wm * 64 + (lane & 15);
    const int laneAc = (lane >> 4);
    const int laneBr = wn * 32 + ((lane & 16) >> 1) + (lane & 7);
    const int laneBc = ((lane >> 3) & 1);

    float acc[4][4][4];
    #pragma unroll
    for (int mt = 0; mt < 4; mt++)
        #pragma unroll
        for (int nt = 0; nt < 4; nt++)
            #pragma unroll
            for (int r = 0; r < 4; r++) acc[mt][nt][r] = 0.f;

    ISSUE(0, 0); CPCOMMIT();
    ISSUE(1, 1); CPCOMMIT();
    ISSUE(2, 2); CPCOMMIT();

    for (int kt = 0; kt < 32; kt++) {
        const int s = kt & 3;
        asm volatile("cp.async.wait_group 2;");
        __syncthreads();
        if (kt + 3 < 32) ISSUE(kt + 3, (kt + 3) & 3);
        CPCOMMIT();

        const uint32_t baseA = asA + (uint32_t)s * (GST * 2);
        const uint32_t baseB = asB + (uint32_t)s * (GST * 2);

        #pragma unroll
        for (int kc = 0; kc < 2; kc++) {
            uint32_t af[4][4], bf[2][4];
            #pragma unroll
            for (int mt = 0; mt < 4; mt++) {
                uint32_t ad = baseA +
                    (uint32_t)(((laneAr + mt * 16) * 32 +
                                (((kc * 2 + laneAc) ^ swf) * 8)) * 2);
                LDSM4(af[mt][0], af[mt][1], af[mt][2], af[mt][3], ad);
            }
            #pragma unroll
            for (int ntp = 0; ntp < 2; ntp++) {
                uint32_t bd = baseB +
                    (uint32_t)(((laneBr + ntp * 16) * 32 +
                                (((kc * 2 + laneBc) ^ swf) * 8)) * 2);
                LDSM4(bf[ntp][0], bf[ntp][1], bf[ntp][2], bf[ntp][3], bd);
            }
            #pragma unroll
            for (int mt = 0; mt < 4; mt++)
                #pragma unroll
                for (int ntp = 0; ntp < 2; ntp++) {
                    mma_f16(acc[mt][ntp * 2 + 0], af[mt], &bf[ntp][0]);
                    mma_f16(acc[mt][ntp * 2 + 1], af[mt], &bf[ntp][2]);
                }
        }
    }
#undef ISSUE

    #pragma unroll
    for (int mt = 0; mt < 4; mt++) {
        int rg = bm + wm * 64 + mt * 16 + li;
        #pragma unroll
        for (int nt = 0; nt < 4; nt++) {
            int cp = bn + wn * 32 + nt * 8 + lc * 2;
            float c0 = acc[mt][nt][0], c1 = acc[mt][nt][1];
            float c2 = acc[mt][nt][2], c3 = acc[mt][nt][3];
            if (applyRope) {
                int   d    = cp & (DHH - 1);
                float freq = powf(10000.0f, -(float)d * (1.0f / 64.0f));
                float s0, co0, s1, co1;
                sincosf((float)(rg & (SS - 1)) * freq, &s0, &co0);
                sincosf((float)((rg + 8) & (SS - 1)) * freq, &s1, &co1);
                float t;
                t  = c0 * co0 - c1 * s0;  c1 = c0 * s0 + c1 * co0;  c0 = t;
                t  = c2 * co1 - c3 * s1;  c3 = c2 * s1 + c3 * co1;  c2 = t;
            }
            c0 *= oscale; c1 *= oscale; c2 *= oscale; c3 *= oscale;
            if (HOUT) {
                __half* Ch = (__half*)Cv;
                *(__half2*)(Ch + (size_t)rg * DD + cp)       = __floats2half2_rn(c0, c1);
                *(__half2*)(Ch + (size_t)(rg + 8) * DD + cp) = __floats2half2_rn(c2, c3);
            } else {
                float* Cf = (float*)Cv;
                *(float2*)(Cf + (size_t)rg * DD + cp)       = make_float2(c0, c1);
                *(float2*)(Cf + (size_t)(rg + 8) * DD + cp) = make_float2(c2, c3);
            }
        }
    }
}

// ---------------------------------------------------------------------------
// fp16 tensor-core causal flash attention.
// Grid (S/128 reversed, B*H), 256 thr = 8 warps, warp = 16 query rows.
// All fragments via ldmatrix from swizzled smem (chunk ^= row&7, 128B rows):
//   QK^T: A = Q (ldsm.x4), B = K rows (ldsm.x2)  [m16n8k16 fp16]
//   P*V : A = P (register repack), B = V via ldsm.x2.trans
// K/V double-buffered with cp.async. Output written as fp16.
// ---------------------------------------------------------------------------
#define AQ_OFF 0
#define AK_OFF 16384
#define AV_OFF 32768
#define AST    8192
#define ATT_SMEM 49152

__global__ __launch_bounds__(256, 2) void attn_h(
    const __half* __restrict__ Q, const __half* __restrict__ K,
    const __half* __restrict__ V, __half* __restrict__ O)
{
    extern __shared__ __align__(16) char smc[];
    const uint32_t smb = smem_u32(smc);

    const int qb   = (int)gridDim.x - 1 - (int)blockIdx.x;   // heavy tiles first
    const int b    = blockIdx.y >> 4;
    const int h    = blockIdx.y & 15;
    const int tid  = threadIdx.x;
    const int w    = tid >> 5;
    const int lane = tid & 31;
    const int li   = lane >> 2;
    const int lc   = lane & 3;
    const size_t base = ((size_t)b * SS) * DD + h * DHH;

    // Load Q tile (128 x 64 half) into swizzled smem
    #pragma unroll
    for (int it = 0; it < 4; it++) {
        int idx = tid + it * 256;           // 1024 chunks
        int row = idx >> 3, ch = idx & 7;
        uint4 u = *(const uint4*)(Q + base + (size_t)(qb * 128 + row) * DD + ch * 8);
        *(uint4*)(smc + AQ_OFF + (row * 8 + (ch ^ (row & 7))) * 16) = u;
    }

    const __half* Kg = K + base;
    const __half* Vg = V + base;

#define KV_ISSUE(kb_, s_) do {                                              \
        uint32_t ko_ = smb + AK_OFF + (uint32_t)(s_) * AST;                 \
        uint32_t vo_ = smb + AV_OFF + (uint32_t)(s_) * AST;                 \
        _Pragma("unroll")                                                   \
        for (int i_ = 0; i_ < 2; i_++) {                                    \
            int idx_ = tid + i_ * 256;                                      \
            int r_ = idx_ >> 3, c_ = idx_ & 7;                              \
            uint32_t d_ = (uint32_t)(r_ * 8 + (c_ ^ (r_ & 7))) * 16;        \
            const __half* sK_ = Kg + (size_t)((kb_) * 64 + r_) * DD + c_ * 8; \
            const __half* sV_ = Vg + (size_t)((kb_) * 64 + r_) * DD + c_ * 8; \
            CP16(ko_ + d_, sK_);                                            \
            CP16(vo_ + d_, sV_);                                            \
        }                                                                   \
        CPCOMMIT();                                                         \
    } while (0)

    float m0 = -1e30f, m1 = -1e30f, l0 = 0.f, l1 = 0.f;
    float o[8][4];
    #pragma unroll
    for (int ot = 0; ot < 8; ot++)
        #pragma unroll
        for (int r = 0; r < 4; r++) o[ot][r] = 0.f;

    const int qlo = qb * 128 + w * 16;
    const int nkv = 2 * qb + 2;

    // ldmatrix lane addressing constants
    const int qrow = w * 16 + (lane & 15);          // A-frag rows
    const int qsw  = lane & 7;                      // row&7 for all recipes
    const uint32_t qbase = smb + AQ_OFF + (uint32_t)(qrow * 8) * 16;
    const int kchunkoff = (lane >> 4);              // A: chunk = 2kc + this
    const int brow = lane & 7;                      // B rows within n8
    const int bchunkoff = (lane >> 3) & 1;          // B: chunk = 2kc + this

    KV_ISSUE(0, 0);

    for (int kb = 0; kb < nkv; kb++) {
        const int s = kb & 1;
        if (kb + 1 < nkv) {
            KV_ISSUE(kb + 1, (kb + 1) & 1);
            asm volatile("cp.async.wait_group 1;");
        } else {
            asm volatile("cp.async.wait_group 0;");
        }
        __syncthreads();

        const uint32_t kbase = smb + AK_OFF + (uint32_t)s * AST;
        const uint32_t vbase = smb + AV_OFF + (uint32_t)s * AST;

        // ---- S = Q K^T ----
        float sc[8][4];
        #pragma unroll
        for (int nt = 0; nt < 8; nt++)
            #pragma unroll
            for (int r = 0; r < 4; r++) sc[nt][r] = 0.f;

        #pragma unroll
        for (int kc = 0; kc < 4; kc++) {
            uint32_t qa[4];
            LDSM4(qa[0], qa[1], qa[2], qa[3],
                  qbase + (uint32_t)(((2 * kc + kchunkoff) ^ qsw) * 16));
            #pragma unroll
            for (int nt = 0; nt < 8; nt++) {
                uint32_t kf[2];
                LDSM2(kf[0], kf[1],
                      kbase + (uint32_t)(((nt * 8 + brow) * 8 +
                               ((2 * kc + bchunkoff) ^ brow)) * 16));
                mma_f16(sc[nt], qa, kf);
            }
        }

        // ---- causal mask (diagonal region only) ----
        if (kb * 64 + 63 > qlo) {
            #pragma unroll
            for (int nt = 0; nt < 8; nt++) {
                int key = kb * 64 + nt * 8 + 2 * lc;
                if (key     > qlo + li)     sc[nt][0] = -1e30f;
                if (key + 1 > qlo + li)     sc[nt][1] = -1e30f;
                if (key     > qlo + li + 8) sc[nt][2] = -1e30f;
                if (key + 1 > qlo + li + 8) sc[nt][3] = -1e30f;
            }
        }

        // ---- online softmax ----
        float mx0 = -1e30f, mx1 = -1e30f;
        #pragma unroll
        for (int nt = 0; nt < 8; nt++) {
            mx0 = fmaxf(mx0, fmaxf(sc[nt][0], sc[nt][1]));
            mx1 = fmaxf(mx1, fmaxf(sc[nt][2], sc[nt][3]));
        }
        mx0 = fmaxf(mx0, __shfl_xor_sync(0xffffffffu, mx0, 1));
        mx0 = fmaxf(mx0, __shfl_xor_sync(0xffffffffu, mx0, 2));
        mx1 = fmaxf(mx1, __shfl_xor_sync(0xffffffffu, mx1, 1));
        mx1 = fmaxf(mx1, __shfl_xor_sync(0xffffffffu, mx1, 2));

        float mn0 = fmaxf(m0, mx0), mn1 = fmaxf(m1, mx1);
        float cr0 = __expf(m0 - mn0), cr1 = __expf(m1 - mn1);
        float rs0 = 0.f, rs1 = 0.f;
        #pragma unroll
        for (int nt = 0; nt < 8; nt++) {
            sc[nt][0] = __expf(sc[nt][0] - mn0); rs0 += sc[nt][0];
            sc[nt][1] = __expf(sc[nt][1] - mn0); rs0 += sc[nt][1];
            sc[nt][2] = __expf(sc[nt][2] - mn1); rs1 += sc[nt][2];
            sc[nt][3] = __expf(sc[nt][3] - mn1); rs1 += sc[nt][3];
        }
        rs0 += __shfl_xor_sync(0xffffffffu, rs0, 1);
        rs0 += __shfl_xor_sync(0xffffffffu, rs0, 2);
        rs1 += __shfl_xor_sync(0xffffffffu, rs1, 1);
        rs1 += __shfl_xor_sync(0xffffffffu, rs1, 2);
        l0 = l0 * cr0 + rs0;  l1 = l1 * cr1 + rs1;
        m0 = mn0;             m1 = mn1;
        #pragma unroll
        for (int ot = 0; ot < 8; ot++) {
            o[ot][0] *= cr0; o[ot][1] *= cr0;
            o[ot][2] *= cr1; o[ot][3] *= cr1;
        }

        // ---- O += P V ----
        #pragma unroll
        for (int j = 0; j < 4; j++) {
            uint32_t pa[4];
            pa[0] = packh2(sc[2*j][0],   sc[2*j][1]);
            pa[1] = packh2(sc[2*j][2],   sc[2*j][3]);
            pa[2] = packh2(sc[2*j+1][0], sc[2*j+1][1]);
            pa[3] = packh2(sc[2*j+1][2], sc[2*j+1][3]);
            int vrow = 16 * j + (lane & 15);
            #pragma unroll
            for (int ot = 0; ot < 8; ot++) {
                uint32_t vf[2];
                LDSM2T(vf[0], vf[1],
                       vbase + (uint32_t)((vrow * 8 + (ot ^ (vrow & 7))) * 16));
                mma_f16(o[ot], pa, vf);
            }
        }
        __syncthreads();   // reads of stage s done before it is refilled
    }
#undef KV_ISSUE

    // epilogue -> fp16 output
    float inv0 = 1.0f / l0, inv1 = 1.0f / l1;
    #pragma unroll
    for (int ot = 0; ot < 8; ot++) {
        int cp = ot * 8 + 2 * lc;
        *(__half2*)(O + base + (size_t)(qlo + li)     * DD + cp) =
            __floats2half2_rn(o[ot][0] * inv0, o[ot][1] * inv0);
        *(__half2*)(O + base + (size_t)(qlo + li + 8) * DD + cp) =
            __floats2half2_rn(o[ot][2] * inv1, o[ot][3] * inv1);
    }
}

// ---------------------------------------------------------------------------
extern "C" void kernel_launch(void* const* d_in, const int* in_sizes, int n_in,
                              void* d_out, int out_size)
{
    const float* x  = (const float*)d_in[0];
    const float* Wq = (const float*)d_in[1];
    const float* Wk = (const float*)d_in[2];
    const float* Wv = (const float*)d_in[3];
    const float* Wo = (const float*)d_in[4];
    float* out = (float*)d_out;

    __half *qh, *kh, *vh, *hoh, *xh, *wqh, *wkh, *wvh, *woh;
    cudaGetSymbolAddress((void**)&qh,  g_qh);
    cudaGetSymbolAddress((void**)&kh,  g_kh);
    cudaGetSymbolAddress((void**)&vh,  g_vh);
    cudaGetSymbolAddress((void**)&hoh, g_hoh);
    cudaGetSymbolAddress((void**)&xh,  g_xh);
    cudaGetSymbolAddress((void**)&wqh, g_wqh);
    cudaGetSymbolAddress((void**)&wkh, g_wkh);
    cudaGetSymbolAddress((void**)&wvh, g_wvh);
    cudaGetSymbolAddress((void**)&woh, g_woh);

    f2h_kernel<<<(MTOT * DD / 8 + 255) / 256, 256>>>(x,  xh,  MTOT * DD);
    f2h_kernel<<<(DD * DD / 8 + 255) / 256, 256>>>(Wq, wqh, DD * DD);
    f2h_kernel<<<(DD * DD / 8 + 255) / 256, 256>>>(Wk, wkh, DD * DD);
    f2h_kernel<<<(DD * DD / 8 + 255) / 256, 256>>>(Wv, wvh, DD * DD);
    f2h_kernel<<<(DD * DD / 8 + 255) / 256, 256>>>(Wo, woh, DD * DD);

    cudaFuncSetAttribute(gemm_h<true>,
                         cudaFuncAttributeMaxDynamicSharedMemorySize, GEMM_SMEM);
    cudaFuncSetAttribute(gemm_h<false>,
                         cudaFuncAttributeMaxDynamicSharedMemorySize, GEMM_SMEM);
    cudaFuncSetAttribute(attn_h,
                         cudaFuncAttributeMaxDynamicSharedMemorySize, ATT_SMEM);

    dim3 gg(DD / 128, MTOT / 128);  // (8, 64)
    gemm_h<true><<<gg, 256, GEMM_SMEM>>>(xh, wqh, qh, 1, 0.125f);
    gemm_h<true><<<gg, 256, GEMM_SMEM>>>(xh, wkh, kh, 1, 1.0f);
    gemm_h<true><<<gg, 256, GEMM_SMEM>>>(xh, wvh, vh, 0, 1.0f);

    attn_h<<<dim3(SS / 128, BB * HH), 256, ATT_SMEM>>>(qh, kh, vh, hoh);

    gemm_h<false><<<gg, 256, GEMM_SMEM>>>(hoh, woh, out, 0, 1.0f);
}

// round 17
// speedup vs baseline: 8.7005x; 1.2180x over previous
#include <cuda_runtime.h>
#include <cuda_fp16.h>
#include <math.h>
#include <stdint.h>

#define BB   4
#define SS   2048
#define DD   1024
#define HH   16
#define DHH  64
#define MTOT (BB*SS)

// Scratch (allocation-free rule: __device__ globals)
__device__ __half g_qh [MTOT*DD];
__device__ __half g_kh [MTOT*DD];
__device__ __half g_vh [MTOT*DD];
__device__ __half g_hoh[MTOT*DD];
__device__ __half g_xh [MTOT*DD];
__device__ __half g_wqh[DD*DD];
__device__ __half g_wkh[DD*DD];
__device__ __half g_wvh[DD*DD];
__device__ __half g_woh[DD*DD];

// ---------------------------------------------------------------------------
// helpers
// ---------------------------------------------------------------------------
__device__ __forceinline__ void mma_f16(float* c, const uint32_t* a, const uint32_t* b) {
    asm volatile(
        "mma.sync.aligned.m16n8k16.row.col.f32.f16.f16.f32 "
        "{%0,%1,%2,%3}, {%4,%5,%6,%7}, {%8,%9}, {%0,%1,%2,%3};"
        : "+f"(c[0]), "+f"(c[1]), "+f"(c[2]), "+f"(c[3])
        : "r"(a[0]), "r"(a[1]), "r"(a[2]), "r"(a[3]),
          "r"(b[0]), "r"(b[1]));
}

__device__ __forceinline__ uint32_t packh2(float lo, float hi) {
    __half2 h = __floats2half2_rn(lo, hi);
    return *(uint32_t*)&h;
}

__device__ __forceinline__ uint32_t smem_u32(const void* p) {
    return (uint32_t)__cvta_generic_to_shared(p);
}

#define CP16(dst, src) \
    asm volatile("cp.async.cg.shared.global [%0], [%1], 16;" :: "r"(dst), "l"(src))
#define CPCOMMIT() asm volatile("cp.async.commit_group;")

#define LDSM4(r0, r1, r2, r3, addr) \
    asm volatile("ldmatrix.sync.aligned.m8n8.x4.shared.b16 {%0,%1,%2,%3}, [%4];" \
                 : "=r"(r0), "=r"(r1), "=r"(r2), "=r"(r3) : "r"(addr))
#define LDSM2(r0, r1, addr) \
    asm volatile("ldmatrix.sync.aligned.m8n8.x2.shared.b16 {%0,%1}, [%2];" \
                 : "=r"(r0), "=r"(r1) : "r"(addr))
#define LDSM2T(r0, r1, addr) \
    asm volatile("ldmatrix.sync.aligned.m8n8.x2.trans.shared.b16 {%0,%1}, [%2];" \
                 : "=r"(r0), "=r"(r1) : "r"(addr))

// ---------------------------------------------------------------------------
// fp32 -> fp16 elementwise converts
// ---------------------------------------------------------------------------
__global__ void f2h_kernel(const float* __restrict__ in, __half* __restrict__ out, int n)
{
    int i = (blockIdx.x * blockDim.x + threadIdx.x) << 3;
    if (i >= n) return;
    float4 v0 = *(const float4*)(in + i);
    float4 v1 = *(const float4*)(in + i + 4);
    __half2 h[4];
    h[0] = __floats2half2_rn(v0.x, v0.y);
    h[1] = __floats2half2_rn(v0.z, v0.w);
    h[2] = __floats2half2_rn(v1.x, v1.y);
    h[3] = __floats2half2_rn(v1.z, v1.w);
    *(uint4*)(out + i) = *(uint4*)h;
}

// all four weight matrices in one launch (blockIdx.y selects)
__global__ void f2h_w4(const float* __restrict__ w0, const float* __restrict__ w1,
                       const float* __restrict__ w2, const float* __restrict__ w3,
                       __half* __restrict__ o0, __half* __restrict__ o1,
                       __half* __restrict__ o2, __half* __restrict__ o3)
{
    const float* in;
    __half* out;
    switch (blockIdx.y) {
        case 0: in = w0; out = o0; break;
        case 1: in = w1; out = o1; break;
        case 2: in = w2; out = o2; break;
        default: in = w3; out = o3; break;
    }
    int i = (blockIdx.x * blockDim.x + threadIdx.x) << 3;
    if (i >= DD * DD) return;
    float4 v0 = *(const float4*)(in + i);
    float4 v1 = *(const float4*)(in + i + 4);
    __half2 h[4];
    h[0] = __floats2half2_rn(v0.x, v0.y);
    h[1] = __floats2half2_rn(v0.z, v0.w);
    h[2] = __floats2half2_rn(v1.x, v1.y);
    h[3] = __floats2half2_rn(v1.z, v1.w);
    *(uint4*)(out + i) = *(uint4*)h;
}

// ---------------------------------------------------------------------------
// NT GEMM core: fp16 in, fp32 accumulate. Block 128x128, K in 16 tiles of 64.
// 3-stage cp.async pipeline, 128B rows with chunk^(row&7) swizzle, ldmatrix.x4.
// ---------------------------------------------------------------------------
#define GSTB     16384                  // bytes per stage per matrix
#define G_BOFF   (3 * GSTB)             // B stages after 3 A stages
#define GEMM_SMEM (6 * GSTB)            // 98304 B

__device__ __forceinline__ void gemm_core(
    const __half* __restrict__ A, const __half* __restrict__ W,
    int bm, int bn, char* smc, float acc[4][4][4])
{
    const uint32_t smb = smem_u32(smc);
    const int tid  = threadIdx.x;
    const int wid  = tid >> 5;
    const int lane = tid & 31;
    const int wm   = wid >> 2;
    const int wn   = wid & 3;

#define GISSUE(kt_, s_) do {                                                   \
        uint32_t ab_ = smb + (uint32_t)(s_) * GSTB;                            \
        uint32_t bb_ = smb + G_BOFF + (uint32_t)(s_) * GSTB;                   \
        _Pragma("unroll")                                                      \
        for (int i_ = 0; i_ < 4; i_++) {                                       \
            int idx_ = tid + i_ * 256;                                         \
            int r_ = idx_ >> 3, c_ = idx_ & 7;                                 \
            uint32_t d_ = (uint32_t)(r_ * 128 + ((c_ ^ (r_ & 7)) * 16));       \
            CP16(ab_ + d_, A + (size_t)(bm + r_) * DD + (kt_) * 64 + c_ * 8);  \
            CP16(bb_ + d_, W + (size_t)(bn + r_) * DD + (kt_) * 64 + c_ * 8);  \
        }                                                                      \
        CPCOMMIT();                                                            \
    } while (0)

    // reader lane mapping (identical fragment semantics to the passing R15 gemm)
    const int laneAr = wm * 64 + (lane & 15);
    const int laneAc = (lane >> 4);
    const int aswz   = laneAr & 7;
    const int laneBr = wn * 32 + ((lane & 16) >> 1) + (lane & 7);
    const int laneBc = ((lane >> 3) & 1);
    const int bswz   = laneBr & 7;

    GISSUE(0, 0);
    GISSUE(1, 1);

    for (int t = 0; t < 16; t++) {
        const int s = t % 3;
        asm volatile("cp.async.wait_group 1;" ::: "memory");
        __syncthreads();
        if (t + 2 < 16) GISSUE(t + 2, (t + 2) % 3);
        else            CPCOMMIT();     // keep group arithmetic constant

        const uint32_t baseA = smb + (uint32_t)s * GSTB;
        const uint32_t baseB = smb + G_BOFF + (uint32_t)s * GSTB;

        #pragma unroll
        for (int kc = 0; kc < 4; kc++) {
            uint32_t af[4][4], bf[2][4];
            #pragma unroll
            for (int mt = 0; mt < 4; mt++) {
                uint32_t ad = baseA + (uint32_t)((laneAr + mt * 16) * 128 +
                                      (((2 * kc + laneAc) ^ aswz) * 16));
                LDSM4(af[mt][0], af[mt][1], af[mt][2], af[mt][3], ad);
            }
            #pragma unroll
            for (int ntp = 0; ntp < 2; ntp++) {
                uint32_t bd = baseB + (uint32_t)((laneBr + ntp * 16) * 128 +
                                      (((2 * kc + laneBc) ^ bswz) * 16));
                LDSM4(bf[ntp][0], bf[ntp][1], bf[ntp][2], bf[ntp][3], bd);
            }
            #pragma unroll
            for (int mt = 0; mt < 4; mt++)
                #pragma unroll
                for (int ntp = 0; ntp < 2; ntp++) {
                    mma_f16(acc[mt][ntp * 2 + 0], af[mt], &bf[ntp][0]);
                    mma_f16(acc[mt][ntp * 2 + 1], af[mt], &bf[ntp][2]);
                }
        }
    }
#undef GISSUE
}

// fused Q/K/V projection: blockIdx.z selects weight/output/rope/scale
__global__ __launch_bounds__(256, 2) void gemm_qkv(
    const __half* __restrict__ X,
    const __half* __restrict__ Wq, const __half* __restrict__ Wk,
    const __half* __restrict__ Wv,
    __half* __restrict__ Qo, __half* __restrict__ Ko, __half* __restrict__ Vo)
{
    extern __shared__ __align__(16) char smc[];
    const int z = blockIdx.z;
    const __half* W = (z == 0) ? Wq : (z == 1) ? Wk : Wv;
    __half* C       = (z == 0) ? Qo : (z == 1) ? Ko : Vo;
    const int applyRope = (z < 2);
    const float oscale  = (z == 0) ? 0.125f : 1.0f;

    const int bm = blockIdx.y * 128;
    const int bn = blockIdx.x * 128;

    float acc[4][4][4];
    #pragma unroll
    for (int mt = 0; mt < 4; mt++)
        #pragma unroll
        for (int nt = 0; nt < 4; nt++)
            #pragma unroll
            for (int r = 0; r < 4; r++) acc[mt][nt][r] = 0.f;

    gemm_core(X, W, bm, bn, smc, acc);

    const int lane = threadIdx.x & 31;
    const int wid  = threadIdx.x >> 5;
    const int wm   = wid >> 2, wn = wid & 3;
    const int li   = lane >> 2, lc = lane & 3;

    #pragma unroll
    for (int mt = 0; mt < 4; mt++) {
        int rg = bm + wm * 64 + mt * 16 + li;
        #pragma unroll
        for (int nt = 0; nt < 4; nt++) {
            int cp = bn + wn * 32 + nt * 8 + lc * 2;
            float c0 = acc[mt][nt][0], c1 = acc[mt][nt][1];
            float c2 = acc[mt][nt][2], c3 = acc[mt][nt][3];
            if (applyRope) {
                int   d    = cp & (DHH - 1);
                float freq = powf(10000.0f, -(float)d * (1.0f / 64.0f));
                float s0, co0, s1, co1;
                sincosf((float)(rg & (SS - 1)) * freq, &s0, &co0);
                sincosf((float)((rg + 8) & (SS - 1)) * freq, &s1, &co1);
                float t;
                t  = c0 * co0 - c1 * s0;  c1 = c0 * s0 + c1 * co0;  c0 = t;
                t  = c2 * co1 - c3 * s1;  c3 = c2 * s1 + c3 * co1;  c2 = t;
            }
            c0 *= oscale; c1 *= oscale; c2 *= oscale; c3 *= oscale;
            *(__half2*)(C + (size_t)rg * DD + cp)       = __floats2half2_rn(c0, c1);
            *(__half2*)(C + (size_t)(rg + 8) * DD + cp) = __floats2half2_rn(c2, c3);
        }
    }
}

// output projection: fp32 out
__global__ __launch_bounds__(256, 2) void gemm_o(
    const __half* __restrict__ A, const __half* __restrict__ W,
    float* __restrict__ C)
{
    extern __shared__ __align__(16) char smc[];
    const int bm = blockIdx.y * 128;
    const int bn = blockIdx.x * 128;

    float acc[4][4][4];
    #pragma unroll
    for (int mt = 0; mt < 4; mt++)
        #pragma unroll
        for (int nt = 0; nt < 4; nt++)
            #pragma unroll
            for (int r = 0; r < 4; r++) acc[mt][nt][r] = 0.f;

    gemm_core(A, W, bm, bn, smc, acc);

    const int lane = threadIdx.x & 31;
    const int wid  = threadIdx.x >> 5;
    const int wm   = wid >> 2, wn = wid & 3;
    const int li   = lane >> 2, lc = lane & 3;

    #pragma unroll
    for (int mt = 0; mt < 4; mt++) {
        int rg = bm + wm * 64 + mt * 16 + li;
        #pragma unroll
        for (int nt = 0; nt < 4; nt++) {
            int cp = bn + wn * 32 + nt * 8 + lc * 2;
            *(float2*)(C + (size_t)rg * DD + cp) =
                make_float2(acc[mt][nt][0], acc[mt][nt][1]);
            *(float2*)(C + (size_t)(rg + 8) * DD + cp) =
                make_float2(acc[mt][nt][2], acc[mt][nt][3]);
        }
    }
}

// ---------------------------------------------------------------------------
// fp16 tensor-core causal flash attention (verbatim R15, known-correct).
// ---------------------------------------------------------------------------
#define AQ_OFF 0
#define AK_OFF 16384
#define AV_OFF 32768
#define AST    8192
#define ATT_SMEM 49152

__global__ __launch_bounds__(256, 2) void attn_h(
    const __half* __restrict__ Q, const __half* __restrict__ K,
    const __half* __restrict__ V, __half* __restrict__ O)
{
    extern __shared__ __align__(16) char smc[];
    const uint32_t smb = smem_u32(smc);

    const int qb   = (int)gridDim.x - 1 - (int)blockIdx.x;
    const int b    = blockIdx.y >> 4;
    const int h    = blockIdx.y & 15;
    const int tid  = threadIdx.x;
    const int w    = tid >> 5;
    const int lane = tid & 31;
    const int li   = lane >> 2;
    const int lc   = lane & 3;
    const size_t base = ((size_t)b * SS) * DD + h * DHH;

    #pragma unroll
    for (int it = 0; it < 4; it++) {
        int idx = tid + it * 256;
        int row = idx >> 3, ch = idx & 7;
        uint4 u = *(const uint4*)(Q + base + (size_t)(qb * 128 + row) * DD + ch * 8);
        *(uint4*)(smc + AQ_OFF + (row * 8 + (ch ^ (row & 7))) * 16) = u;
    }

    const __half* Kg = K + base;
    const __half* Vg = V + base;

#define KV_ISSUE(kb_, s_) do {                                              \
        uint32_t ko_ = smb + AK_OFF + (uint32_t)(s_) * AST;                 \
        uint32_t vo_ = smb + AV_OFF + (uint32_t)(s_) * AST;                 \
        _Pragma("unroll")                                                   \
        for (int i_ = 0; i_ < 2; i_++) {                                    \
            int idx_ = tid + i_ * 256;                                      \
            int r_ = idx_ >> 3, c_ = idx_ & 7;                              \
            uint32_t d_ = (uint32_t)(r_ * 8 + (c_ ^ (r_ & 7))) * 16;        \
            const __half* sK_ = Kg + (size_t)((kb_) * 64 + r_) * DD + c_ * 8; \
            const __half* sV_ = Vg + (size_t)((kb_) * 64 + r_) * DD + c_ * 8; \
            CP16(ko_ + d_, sK_);                                            \
            CP16(vo_ + d_, sV_);                                            \
        }                                                                   \
        CPCOMMIT();                                                         \
    } while (0)

    float m0 = -1e30f, m1 = -1e30f, l0 = 0.f, l1 = 0.f;
    float o[8][4];
    #pragma unroll
    for (int ot = 0; ot < 8; ot++)
        #pragma unroll
        for (int r = 0; r < 4; r++) o[ot][r] = 0.f;

    const int qlo = qb * 128 + w * 16;
    const int nkv = 2 * qb + 2;

    const int qrow = w * 16 + (lane & 15);
    const int qsw  = lane & 7;
    const uint32_t qbase = smb + AQ_OFF + (uint32_t)(qrow * 8) * 16;
    const int kchunkoff = (lane >> 4);
    const int brow = lane & 7;
    const int bchunkoff = (lane >> 3) & 1;

    KV_ISSUE(0, 0);

    for (int kb = 0; kb < nkv; kb++) {
        const int s = kb & 1;
        if (kb + 1 < nkv) {
            KV_ISSUE(kb + 1, (kb + 1) & 1);
            asm volatile("cp.async.wait_group 1;");
        } else {
            asm volatile("cp.async.wait_group 0;");
        }
        __syncthreads();

        const uint32_t kbase = smb + AK_OFF + (uint32_t)s * AST;
        const uint32_t vbase = smb + AV_OFF + (uint32_t)s * AST;

        float sc[8][4];
        #pragma unroll
        for (int nt = 0; nt < 8; nt++)
            #pragma unroll
            for (int r = 0; r < 4; r++) sc[nt][r] = 0.f;

        #pragma unroll
        for (int kc = 0; kc < 4; kc++) {
            uint32_t qa[4];
            LDSM4(qa[0], qa[1], qa[2], qa[3],
                  qbase + (uint32_t)(((2 * kc + kchunkoff) ^ qsw) * 16));
            #pragma unroll
            for (int nt = 0; nt < 8; nt++) {
                uint32_t kf[2];
                LDSM2(kf[0], kf[1],
                      kbase + (uint32_t)(((nt * 8 + brow) * 8 +
                               ((2 * kc + bchunkoff) ^ brow)) * 16));
                mma_f16(sc[nt], qa, kf);
            }
        }

        if (kb * 64 + 63 > qlo) {
            #pragma unroll
            for (int nt = 0; nt < 8; nt++) {
                int key = kb * 64 + nt * 8 + 2 * lc;
                if (key     > qlo + li)     sc[nt][0] = -1e30f;
                if (key + 1 > qlo + li)     sc[nt][1] = -1e30f;
                if (key     > qlo + li + 8) sc[nt][2] = -1e30f;
                if (key + 1 > qlo + li + 8) sc[nt][3] = -1e30f;
            }
        }

        float mx0 = -1e30f, mx1 = -1e30f;
        #pragma unroll
        for (int nt = 0; nt < 8; nt++) {
            mx0 = fmaxf(mx0, fmaxf(sc[nt][0], sc[nt][1]));
            mx1 = fmaxf(mx1, fmaxf(sc[nt][2], sc[nt][3]));
        }
        mx0 = fmaxf(mx0, __shfl_xor_sync(0xffffffffu, mx0, 1));
        mx0 = fmaxf(mx0, __shfl_xor_sync(0xffffffffu, mx0, 2));
        mx1 = fmaxf(mx1, __shfl_xor_sync(0xffffffffu, mx1, 1));
        mx1 = fmaxf(mx1, __shfl_xor_sync(0xffffffffu, mx1, 2));

        float mn0 = fmaxf(m0, mx0), mn1 = fmaxf(m1, mx1);
        float cr0 = __expf(m0 - mn0), cr1 = __expf(m1 - mn1);
        float rs0 = 0.f, rs1 = 0.f;
        #pragma unroll
        for (int nt = 0; nt < 8; nt++) {
            sc[nt][0] = __expf(sc[nt][0] - mn0); rs0 += sc[nt][0];
            sc[nt][1] = __expf(sc[nt][1] - mn0); rs0 += sc[nt][1];
            sc[nt][2] = __expf(sc[nt][2] - mn1); rs1 += sc[nt][2];
            sc[nt][3] = __expf(sc[nt][3] - mn1); rs1 += sc[nt][3];
        }
        rs0 += __shfl_xor_sync(0xffffffffu, rs0, 1);
        rs0 += __shfl_xor_sync(0xffffffffu, rs0, 2);
        rs1 += __shfl_xor_sync(0xffffffffu, rs1, 1);
        rs1 += __shfl_xor_sync(0xffffffffu, rs1, 2);
        l0 = l0 * cr0 + rs0;  l1 = l1 * cr1 + rs1;
        m0 = mn0;             m1 = mn1;
        #pragma unroll
        for (int ot = 0; ot < 8; ot++) {
            o[ot][0] *= cr0; o[ot][1] *= cr0;
            o[ot][2] *= cr1; o[ot][3] *= cr1;
        }

        #pragma unroll
        for (int j = 0; j < 4; j++) {
            uint32_t pa[4];
            pa[0] = packh2(sc[2*j][0],   sc[2*j][1]);
            pa[1] = packh2(sc[2*j][2],   sc[2*j][3]);
            pa[2] = packh2(sc[2*j+1][0], sc[2*j+1][1]);
            pa[3] = packh2(sc[2*j+1][2], sc[2*j+1][3]);
            int vrow = 16 * j + (lane & 15);
            #pragma unroll
            for (int ot = 0; ot < 8; ot++) {
                uint32_t vf[2];
                LDSM2T(vf[0], vf[1],
                       vbase + (uint32_t)((vrow * 8 + (ot ^ (vrow & 7))) * 16));
                mma_f16(o[ot], pa, vf);
            }
        }
        __syncthreads();
    }
#undef KV_ISSUE

    float inv0 = 1.0f / l0, inv1 = 1.0f / l1;
    #pragma unroll
    for (int ot = 0; ot < 8; ot++) {
        int cp = ot * 8 + 2 * lc;
        *(__half2*)(O + base + (size_t)(qlo + li)     * DD + cp) =
            __floats2half2_rn(o[ot][0] * inv0, o[ot][1] * inv0);
        *(__half2*)(O + base + (size_t)(qlo + li + 8) * DD + cp) =
            __floats2half2_rn(o[ot][2] * inv1, o[ot][3] * inv1);
    }
}

// ---------------------------------------------------------------------------
extern "C" void kernel_launch(void* const* d_in, const int* in_sizes, int n_in,
                              void* d_out, int out_size)
{
    const float* x  = (const float*)d_in[0];
    const float* Wq = (const float*)d_in[1];
    const float* Wk = (const float*)d_in[2];
    const float* Wv = (const float*)d_in[3];
    const float* Wo = (const float*)d_in[4];
    float* out = (float*)d_out;

    __half *qh, *kh, *vh, *hoh, *xh, *wqh, *wkh, *wvh, *woh;
    cudaGetSymbolAddress((void**)&qh,  g_qh);
    cudaGetSymbolAddress((void**)&kh,  g_kh);
    cudaGetSymbolAddress((void**)&vh,  g_vh);
    cudaGetSymbolAddress((void**)&hoh, g_hoh);
    cudaGetSymbolAddress((void**)&xh,  g_xh);
    cudaGetSymbolAddress((void**)&wqh, g_wqh);
    cudaGetSymbolAddress((void**)&wkh, g_wkh);
    cudaGetSymbolAddress((void**)&wvh, g_wvh);
    cudaGetSymbolAddress((void**)&woh, g_woh);

    f2h_kernel<<<(MTOT * DD / 8 + 255) / 256, 256>>>(x, xh, MTOT * DD);
    f2h_w4<<<dim3((DD * DD / 8 + 255) / 256, 4), 256>>>(
        Wq, Wk, Wv, Wo, wqh, wkh, wvh, woh);

    cudaFuncSetAttribute(gemm_qkv,
                         cudaFuncAttributeMaxDynamicSharedMemorySize, GEMM_SMEM);
    cudaFuncSetAttribute(gemm_o,
                         cudaFuncAttributeMaxDynamicSharedMemorySize, GEMM_SMEM);
    cudaFuncSetAttribute(attn_h,
                         cudaFuncAttributeMaxDynamicSharedMemorySize, ATT_SMEM);

    gemm_qkv<<<dim3(DD / 128, MTOT / 128, 3), 256, GEMM_SMEM>>>(
        xh, wqh, wkh, wvh, qh, kh, vh);

    attn_h<<<dim3(SS / 128, BB * HH), 256, ATT_SMEM>>>(qh, kh, vh, hoh);

    gemm_o<<<dim3(DD / 128, MTOT / 128), 256, GEMM_SMEM>>>(hoh, woh, out);
}